// round 4
// baseline (speedup 1.0000x reference)
#include <cuda_runtime.h>

#define BT 4096
#define T_ 1024
#define E_ 512
#define H_ 8
#define DH 64
#define L_ 8
#define V_ 128
#define EPS_ 0.1f

// ---------------- scratch (device globals; no allocations allowed) ----------
__device__ float g_x[BT * E_];        // residual stream
__device__ float g_qkv[BT * 3 * E_];  // qkv projections (also head scratch)
__device__ float g_a[BT * E_];        // attention output
__device__ float g_h[BT * E_];        // hidden (relu) buffer
__device__ float g_b2[BT * E_];       // second proj buffer
__device__ float g_o1[BT * E_];       // out1 (post-LN1)
__device__ int   g_is64[2];           // dtype flags for inputs/targets

// ---------------- int64-vs-int32 detection ---------------------------------
// If the buffer is int64 little-endian with small nonneg values, every odd
// int32 word (high word) is zero. If int32, odd words are random tokens.
__global__ void detect_kernel(const int* __restrict__ p, int n, int slot) {
    __shared__ int red[256];
    int acc = 0;
    for (int j = 2 * threadIdx.x + 1; j < n; j += 512) acc |= p[j];
    red[threadIdx.x] = acc;
    __syncthreads();
    for (int s = 128; s > 0; s >>= 1) {
        if (threadIdx.x < s) red[threadIdx.x] |= red[threadIdx.x + s];
        __syncthreads();
    }
    if (threadIdx.x == 0) g_is64[slot] = (red[0] == 0) ? 1 : 0;
}

// ---------------- embedding gather ------------------------------------------
__global__ void embed_kernel(const int* __restrict__ inp, const float* __restrict__ emb) {
    int t = blockIdx.x;
    int tok = g_is64[0] ? inp[2 * t] : inp[t];
    const float4* src = (const float4*)(emb + (size_t)tok * E_);
    float4* dst = (float4*)(g_x + (size_t)t * E_);
    for (int i = threadIdx.x; i < E_ / 4; i += blockDim.x) dst[i] = src[i];
}

// ---------------- tiled SGEMM: C[M,N] = A[M,K] * B[N,K]^T + bias ------------
// BM=BN=64, BK=16, 256 threads, 4x4 register tile per thread.
template <int RELU>
__global__ __launch_bounds__(256) void sgemm_nt(
    const float* __restrict__ A, const float* __restrict__ B,
    const float* __restrict__ bias, float* __restrict__ C, int N, int K) {
    __shared__ float As[16][64];
    __shared__ float Bs[16][64];
    int tid = threadIdx.x;
    int tx = tid & 15, ty = tid >> 4;
    int m0 = blockIdx.y * 64, n0 = blockIdx.x * 64;
    int lr = tid >> 2;         // 0..63 row within tile
    int lc = (tid & 3) * 4;    // k offset within 16-chunk
    const float* Ap = A + (size_t)(m0 + lr) * K + lc;
    const float* Bp = B + (size_t)(n0 + lr) * K + lc;
    float acc[4][4] = {};
    for (int k0 = 0; k0 < K; k0 += 16) {
        float4 a = *(const float4*)(Ap + k0);
        float4 b = *(const float4*)(Bp + k0);
        As[lc + 0][lr] = a.x; As[lc + 1][lr] = a.y; As[lc + 2][lr] = a.z; As[lc + 3][lr] = a.w;
        Bs[lc + 0][lr] = b.x; Bs[lc + 1][lr] = b.y; Bs[lc + 2][lr] = b.z; Bs[lc + 3][lr] = b.w;
        __syncthreads();
#pragma unroll
        for (int kk = 0; kk < 16; kk++) {
            float4 av = *(const float4*)&As[kk][ty * 4];
            float4 bv = *(const float4*)&Bs[kk][tx * 4];
            float ar[4] = {av.x, av.y, av.z, av.w};
            float br[4] = {bv.x, bv.y, bv.z, bv.w};
#pragma unroll
            for (int i = 0; i < 4; i++)
#pragma unroll
                for (int j = 0; j < 4; j++) acc[i][j] += ar[i] * br[j];
        }
        __syncthreads();
    }
    float b0 = bias[n0 + tx * 4 + 0];
    float b1 = bias[n0 + tx * 4 + 1];
    float b2 = bias[n0 + tx * 4 + 2];
    float b3 = bias[n0 + tx * 4 + 3];
#pragma unroll
    for (int i = 0; i < 4; i++) {
        float4 v;
        v.x = acc[i][0] + b0; v.y = acc[i][1] + b1;
        v.z = acc[i][2] + b2; v.w = acc[i][3] + b3;
        if (RELU) {
            v.x = fmaxf(v.x, 0.f); v.y = fmaxf(v.y, 0.f);
            v.z = fmaxf(v.z, 0.f); v.w = fmaxf(v.w, 0.f);
        }
        *(float4*)&C[(size_t)(m0 + ty * 4 + i) * N + n0 + tx * 4] = v;
    }
}

// ---------------- flash attention with multiply-mask semantics --------------
// scores = (q.k)*scale for k<=q, EXACTLY 0 for k>q; softmax over ALL T keys
// (masked positions contribute exp(0-m) weight AND their V rows).
__global__ __launch_bounds__(256) void attn_kernel(
    const float* __restrict__ qkv, float* __restrict__ out) {
    __shared__ float Qs[64][64];   // [d][q]
    __shared__ float KPs[64][64];  // K as [d][k]; reused as P [q][k]
    __shared__ float Vs[64][64];   // [k][d]
    int tid = threadIdx.x, tx = tid & 15, ty = tid >> 4;
    int qt = blockIdx.x, bh = blockIdx.y;
    int b = bh >> 3, h = bh & 7;
    const float* base = qkv + (size_t)b * T_ * 1536 + h * 192;
    int q0 = qt * 64;
    int lr = tid >> 2;          // 0..63
    int c0 = (tid & 3) * 16;    // col group
    {
        const float* qp = base + (size_t)(q0 + lr) * 1536;
#pragma unroll
        for (int u = 0; u < 4; u++) {
            float4 v = *(const float4*)(qp + c0 + 4 * u);
            Qs[c0 + 4 * u + 0][lr] = v.x; Qs[c0 + 4 * u + 1][lr] = v.y;
            Qs[c0 + 4 * u + 2][lr] = v.z; Qs[c0 + 4 * u + 3][lr] = v.w;
        }
    }
    float m[4], l[4], o[4][4];
#pragma unroll
    for (int i = 0; i < 4; i++) {
        m[i] = -1e30f; l[i] = 0.f;
#pragma unroll
        for (int j = 0; j < 4; j++) o[i][j] = 0.f;
    }
    for (int kt = 0; kt < 16; kt++) {
        __syncthreads();  // Q done (first iter); P@V reads of KPs done (later iters)
        {
            const float* kp = base + (size_t)(kt * 64 + lr) * 1536 + 64;
            const float* vp = base + (size_t)(kt * 64 + lr) * 1536 + 128;
#pragma unroll
            for (int u = 0; u < 4; u++) {
                float4 kv = *(const float4*)(kp + c0 + 4 * u);
                KPs[c0 + 4 * u + 0][lr] = kv.x; KPs[c0 + 4 * u + 1][lr] = kv.y;
                KPs[c0 + 4 * u + 2][lr] = kv.z; KPs[c0 + 4 * u + 3][lr] = kv.w;
                *(float4*)&Vs[lr][c0 + 4 * u] = *(const float4*)(vp + c0 + 4 * u);
            }
        }
        __syncthreads();
        float s[4][4] = {};
        bool any_unmasked = (kt * 64 <= q0 + 63);
        if (any_unmasked) {
#pragma unroll
            for (int kk = 0; kk < 64; kk++) {
                float4 av = *(const float4*)&Qs[kk][ty * 4];
                float4 bv = *(const float4*)&KPs[kk][tx * 4];
                float ar[4] = {av.x, av.y, av.z, av.w};
                float br[4] = {bv.x, bv.y, bv.z, bv.w};
#pragma unroll
                for (int i = 0; i < 4; i++)
#pragma unroll
                    for (int j = 0; j < 4; j++) s[i][j] += ar[i] * br[j];
            }
        }
        float p[4][4];
#pragma unroll
        for (int i = 0; i < 4; i++) {
            int qpos = q0 + ty * 4 + i;
            float mt = -1e30f;
#pragma unroll
            for (int j = 0; j < 4; j++) {
                int kpos = kt * 64 + tx * 4 + j;
                float sv = (kpos <= qpos) ? s[i][j] * 0.125f : 0.f;
                s[i][j] = sv;
                mt = fmaxf(mt, sv);
            }
#pragma unroll
            for (int ofs = 1; ofs < 16; ofs <<= 1)
                mt = fmaxf(mt, __shfl_xor_sync(0xffffffffu, mt, ofs));
            float mn = fmaxf(m[i], mt);
            float alpha = __expf(m[i] - mn);
            m[i] = mn;
            float ps = 0.f;
#pragma unroll
            for (int j = 0; j < 4; j++) {
                p[i][j] = __expf(s[i][j] - mn);
                ps += p[i][j];
            }
#pragma unroll
            for (int ofs = 1; ofs < 16; ofs <<= 1)
                ps += __shfl_xor_sync(0xffffffffu, ps, ofs);
            l[i] = l[i] * alpha + ps;
#pragma unroll
            for (int j = 0; j < 4; j++) o[i][j] *= alpha;
        }
        __syncthreads();  // all S-gemm reads of KPs finished
#pragma unroll
        for (int i = 0; i < 4; i++)
            *(float4*)&KPs[ty * 4 + i][tx * 4] =
                make_float4(p[i][0], p[i][1], p[i][2], p[i][3]);
        __syncthreads();
#pragma unroll
        for (int kk = 0; kk < 64; kk++) {
            float a0 = KPs[ty * 4 + 0][kk];
            float a1 = KPs[ty * 4 + 1][kk];
            float a2 = KPs[ty * 4 + 2][kk];
            float a3 = KPs[ty * 4 + 3][kk];
            float4 bv = *(const float4*)&Vs[kk][tx * 4];
            float br[4] = {bv.x, bv.y, bv.z, bv.w};
#pragma unroll
            for (int j = 0; j < 4; j++) {
                o[0][j] += a0 * br[j]; o[1][j] += a1 * br[j];
                o[2][j] += a2 * br[j]; o[3][j] += a3 * br[j];
            }
        }
    }
    float* op = out + (size_t)(b * T_ + q0) * E_ + h * 64;
#pragma unroll
    for (int i = 0; i < 4; i++) {
        float inv = 1.f / l[i];
        *(float4*)(op + (size_t)(ty * 4 + i) * E_ + tx * 4) =
            make_float4(o[i][0] * inv, o[i][1] * inv, o[i][2] * inv, o[i][3] * inv);
    }
}

// ---------------- fused residual-add + layernorm ----------------------------
__global__ __launch_bounds__(128) void add_ln_kernel(
    const float* __restrict__ A, const float* __restrict__ R,
    const float* __restrict__ sc, const float* __restrict__ bi,
    float* __restrict__ out) {
    __shared__ float red[4], red2[4];
    int t = blockIdx.x, tid = threadIdx.x;
    int e0 = tid * 4;
    float4 a = *(const float4*)&A[(size_t)t * E_ + e0];
    float4 r = *(const float4*)&R[(size_t)t * E_ + e0];
    float v0 = a.x + r.x, v1 = a.y + r.y, v2 = a.z + r.z, v3 = a.w + r.w;
    float sum = v0 + v1 + v2 + v3;
#pragma unroll
    for (int o = 16; o; o >>= 1) sum += __shfl_xor_sync(0xffffffffu, sum, o);
    int w = tid >> 5, lane = tid & 31;
    if (lane == 0) red[w] = sum;
    __syncthreads();
    sum = red[0] + red[1] + red[2] + red[3];
    float mu = sum * (1.f / E_);
    float d0 = v0 - mu, d1 = v1 - mu, d2 = v2 - mu, d3 = v3 - mu;
    float sq = d0 * d0 + d1 * d1 + d2 * d2 + d3 * d3;
#pragma unroll
    for (int o = 16; o; o >>= 1) sq += __shfl_xor_sync(0xffffffffu, sq, o);
    if (lane == 0) red2[w] = sq;
    __syncthreads();
    sq = red2[0] + red2[1] + red2[2] + red2[3];
    float rstd = rsqrtf(sq * (1.f / E_) + 1e-5f);
    float4 s4 = *(const float4*)&sc[e0];
    float4 b4 = *(const float4*)&bi[e0];
    float4 o4;
    o4.x = d0 * rstd * s4.x + b4.x;
    o4.y = d1 * rstd * s4.y + b4.y;
    o4.z = d2 * rstd * s4.z + b4.z;
    o4.w = d3 * rstd * s4.w + b4.w;
    *(float4*)&out[(size_t)t * E_ + e0] = o4;
}

// ---------------- loss ------------------------------------------------------
__global__ void zero_loss(float* p) { *p = 0.f; }

__global__ __launch_bounds__(256) void loss_kernel(
    const float* __restrict__ logits, const int* __restrict__ tgt,
    float* __restrict__ loss_out) {
    int warp = threadIdx.x >> 5, lane = threadIdx.x & 31;
    int t = blockIdx.x * 8 + warp;
    const float* lp = logits + (size_t)t * V_;
    float x[4];
    float mx = -1e30f, tot = 0.f;
#pragma unroll
    for (int i = 0; i < 4; i++) {
        x[i] = lp[lane + 32 * i];
        mx = fmaxf(mx, x[i]);
        tot += x[i];
    }
#pragma unroll
    for (int o = 16; o; o >>= 1) mx = fmaxf(mx, __shfl_xor_sync(0xffffffffu, mx, o));
    float s = 0.f;
#pragma unroll
    for (int i = 0; i < 4; i++) s += expf(x[i] - mx);
#pragma unroll
    for (int o = 16; o; o >>= 1) {
        s += __shfl_xor_sync(0xffffffffu, s, o);
        tot += __shfl_xor_sync(0xffffffffu, tot, o);
    }
    if (lane == 0) {
        float logZ = mx + logf(s);
        int tv = g_is64[1] ? tgt[2 * t] : tgt[t];
        float nll = logZ - lp[tv];
        float smooth = logZ - tot * (1.f / V_);
        atomicAdd(loss_out, ((1.f - EPS_) * nll + EPS_ * smooth) * (1.f / BT));
    }
}

// ---------------- driver -----------------------------------------------------
extern "C" void kernel_launch(void* const* d_in, const int* in_sizes, int n_in,
                              void* d_out, int out_size) {
    const int*   inputs  = (const int*)d_in[0];
    const int*   targets = (const int*)d_in[1];
    const float* emb     = (const float*)d_in[2];
    const float* qkv_w   = (const float*)d_in[3];
    const float* qkv_b   = (const float*)d_in[4];
    const float* aff1_w  = (const float*)d_in[5];
    const float* aff1_b  = (const float*)d_in[6];
    const float* aff2_w  = (const float*)d_in[7];
    const float* aff2_b  = (const float*)d_in[8];
    const float* ffn1_w  = (const float*)d_in[9];
    const float* ffn1_b  = (const float*)d_in[10];
    const float* ffn2_w  = (const float*)d_in[11];
    const float* ffn2_b  = (const float*)d_in[12];
    const float* ln1_s   = (const float*)d_in[13];
    const float* ln1_b   = (const float*)d_in[14];
    const float* ln2_s   = (const float*)d_in[15];
    const float* ln2_b   = (const float*)d_in[16];
    const float* head_w  = (const float*)d_in[17];
    const float* head_b  = (const float*)d_in[18];
    float* out = (float*)d_out;

    float *px, *pqkv, *pa, *ph, *pb, *po1;
    cudaGetSymbolAddress((void**)&px,  g_x);
    cudaGetSymbolAddress((void**)&pqkv, g_qkv);
    cudaGetSymbolAddress((void**)&pa,  g_a);
    cudaGetSymbolAddress((void**)&ph,  g_h);
    cudaGetSymbolAddress((void**)&pb,  g_b2);
    cudaGetSymbolAddress((void**)&po1, g_o1);

    detect_kernel<<<1, 256>>>(inputs, BT, 0);
    detect_kernel<<<1, 256>>>(targets, BT, 1);
    embed_kernel<<<BT, 128>>>(inputs, emb);

    for (int l = 0; l < L_; l++) {
        sgemm_nt<0><<<dim3(24, 64), 256>>>(px, qkv_w + (size_t)l * 1536 * 512,
                                           qkv_b + (size_t)l * 1536, pqkv, 1536, 512);
        attn_kernel<<<dim3(16, 32), 256>>>(pqkv, pa);
        sgemm_nt<1><<<dim3(8, 64), 256>>>(pa, aff1_w + (size_t)l * 512 * 512,
                                          aff1_b + (size_t)l * 512, ph, 512, 512);
        sgemm_nt<0><<<dim3(8, 64), 256>>>(ph, aff2_w + (size_t)l * 512 * 512,
                                          aff2_b + (size_t)l * 512, pb, 512, 512);
        add_ln_kernel<<<BT, 128>>>(pb, px, ln1_s + (size_t)l * 512,
                                   ln1_b + (size_t)l * 512, po1);
        sgemm_nt<1><<<dim3(8, 64), 256>>>(po1, ffn1_w + (size_t)l * 512 * 512,
                                          ffn1_b + (size_t)l * 512, ph, 512, 512);
        sgemm_nt<0><<<dim3(8, 64), 256>>>(ph, ffn2_w + (size_t)l * 512 * 512,
                                          ffn2_b + (size_t)l * 512, pb, 512, 512);
        add_ln_kernel<<<BT, 128>>>(po1, pb, ln2_s + (size_t)l * 512,
                                   ln2_b + (size_t)l * 512, px);
    }

    // Head: write logits into d_out if it fits, else into scratch.
    float* logits_dst = (out_size >= BT * V_) ? out : pqkv;
    sgemm_nt<0><<<dim3(2, 64), 256>>>(px, head_w, head_b, logits_dst, V_, 512);

    // Loss scalar (after logits, if there is room; or alone if out is tiny).
    float* loss_dst = nullptr;
    if (out_size > BT * V_) loss_dst = out + BT * V_;
    else if (out_size < BT * V_ && out_size >= 1) loss_dst = out;
    if (loss_dst) {
        zero_loss<<<1, 1>>>(loss_dst);
        loss_kernel<<<BT / 8, 256>>>(logits_dst, targets, loss_dst);
    }
}

// round 6
// speedup vs baseline: 1.1538x; 1.1538x over previous
#include <cuda_runtime.h>

#define BT 4096
#define T_ 1024
#define E_ 512
#define H_ 8
#define DH 64
#define L_ 8
#define V_ 128
#define EPS_ 0.1f

// ---------------- scratch (device globals; no allocations allowed) ----------
__device__ float g_x[BT * E_];        // residual stream
__device__ float g_qkv[BT * 3 * E_];  // qkv projections (also head scratch)
__device__ float g_a[BT * E_];        // attention output
__device__ float g_h[BT * E_];        // hidden (relu) buffer
__device__ float g_b2[BT * E_];       // second proj buffer
__device__ float g_o1[BT * E_];       // out1 (post-LN1)
__device__ int   g_is64[2];           // dtype flags for inputs/targets

// ---------------- int64-vs-int32 detection ---------------------------------
__global__ void detect_kernel(const int* __restrict__ p, int n, int slot) {
    __shared__ int red[256];
    int acc = 0;
    for (int j = 2 * threadIdx.x + 1; j < n; j += 512) acc |= p[j];
    red[threadIdx.x] = acc;
    __syncthreads();
    for (int s = 128; s > 0; s >>= 1) {
        if (threadIdx.x < s) red[threadIdx.x] |= red[threadIdx.x + s];
        __syncthreads();
    }
    if (threadIdx.x == 0) g_is64[slot] = (red[0] == 0) ? 1 : 0;
}

// ---------------- embedding gather ------------------------------------------
__global__ void embed_kernel(const int* __restrict__ inp, const float* __restrict__ emb) {
    int t = blockIdx.x;
    int tok = g_is64[0] ? inp[2 * t] : inp[t];
    const float4* src = (const float4*)(emb + (size_t)tok * E_);
    float4* dst = (float4*)(g_x + (size_t)t * E_);
    for (int i = threadIdx.x; i < E_ / 4; i += blockDim.x) dst[i] = src[i];
}

// ---------------- 128x128x8 SGEMM: C[M,N] = A[M,K] * B[N,K]^T + bias --------
// 256 threads, 8x8 register tile per thread, reg-prefetch double buffering.
// 64 FMA per 64 smem bytes per thread-step -> FMA-bound, not L1-bound.
template <int RELU>
__global__ __launch_bounds__(256) void sgemm128(
    const float* __restrict__ A, const float* __restrict__ B,
    const float* __restrict__ bias, float* __restrict__ C, int N, int K) {
    __shared__ float As[8][128];
    __shared__ float Bs[8][128];
    int tid = threadIdx.x;
    int m0 = blockIdx.y * 128, n0 = blockIdx.x * 128;
    int lr = tid >> 1;             // 0..127 tile row
    int lk = (tid & 1) * 4;        // k offset 0 or 4
    const float* Ap = A + (size_t)(m0 + lr) * K + lk;
    const float* Bp = B + (size_t)(n0 + lr) * K + lk;
    int tx = tid & 15, ty = tid >> 4;

    float acc[8][8] = {};
    float4 a_reg = *(const float4*)(Ap);
    float4 b_reg = *(const float4*)(Bp);

    for (int k0 = 0; k0 < K; k0 += 8) {
        As[lk + 0][lr] = a_reg.x; As[lk + 1][lr] = a_reg.y;
        As[lk + 2][lr] = a_reg.z; As[lk + 3][lr] = a_reg.w;
        Bs[lk + 0][lr] = b_reg.x; Bs[lk + 1][lr] = b_reg.y;
        Bs[lk + 2][lr] = b_reg.z; Bs[lk + 3][lr] = b_reg.w;
        __syncthreads();
        if (k0 + 8 < K) {
            a_reg = *(const float4*)(Ap + k0 + 8);
            b_reg = *(const float4*)(Bp + k0 + 8);
        }
#pragma unroll
        for (int kk = 0; kk < 8; kk++) {
            float4 a0 = *(const float4*)&As[kk][ty * 8];
            float4 a1 = *(const float4*)&As[kk][ty * 8 + 4];
            float4 b0 = *(const float4*)&Bs[kk][tx * 8];
            float4 b1 = *(const float4*)&Bs[kk][tx * 8 + 4];
            float ar[8] = {a0.x, a0.y, a0.z, a0.w, a1.x, a1.y, a1.z, a1.w};
            float br[8] = {b0.x, b0.y, b0.z, b0.w, b1.x, b1.y, b1.z, b1.w};
#pragma unroll
            for (int i = 0; i < 8; i++)
#pragma unroll
                for (int j = 0; j < 8; j++) acc[i][j] += ar[i] * br[j];
        }
        __syncthreads();
    }

    float brg[8];
#pragma unroll
    for (int j = 0; j < 8; j++) brg[j] = bias[n0 + tx * 8 + j];
#pragma unroll
    for (int i = 0; i < 8; i++) {
        float* cp = &C[(size_t)(m0 + ty * 8 + i) * N + n0 + tx * 8];
        float4 v0, v1;
        v0.x = acc[i][0] + brg[0]; v0.y = acc[i][1] + brg[1];
        v0.z = acc[i][2] + brg[2]; v0.w = acc[i][3] + brg[3];
        v1.x = acc[i][4] + brg[4]; v1.y = acc[i][5] + brg[5];
        v1.z = acc[i][6] + brg[6]; v1.w = acc[i][7] + brg[7];
        if (RELU) {
            v0.x = fmaxf(v0.x, 0.f); v0.y = fmaxf(v0.y, 0.f);
            v0.z = fmaxf(v0.z, 0.f); v0.w = fmaxf(v0.w, 0.f);
            v1.x = fmaxf(v1.x, 0.f); v1.y = fmaxf(v1.y, 0.f);
            v1.z = fmaxf(v1.z, 0.f); v1.w = fmaxf(v1.w, 0.f);
        }
        *(float4*)cp = v0;
        *(float4*)(cp + 4) = v1;
    }
}

// ---------------- small SGEMM (head, N=128): 64x64x16 tile ------------------
template <int RELU>
__global__ __launch_bounds__(256) void sgemm_nt(
    const float* __restrict__ A, const float* __restrict__ B,
    const float* __restrict__ bias, float* __restrict__ C, int N, int K) {
    __shared__ float As[16][64];
    __shared__ float Bs[16][64];
    int tid = threadIdx.x;
    int tx = tid & 15, ty = tid >> 4;
    int m0 = blockIdx.y * 64, n0 = blockIdx.x * 64;
    int lr = tid >> 2;
    int lc = (tid & 3) * 4;
    const float* Ap = A + (size_t)(m0 + lr) * K + lc;
    const float* Bp = B + (size_t)(n0 + lr) * K + lc;
    float acc[4][4] = {};
    for (int k0 = 0; k0 < K; k0 += 16) {
        float4 a = *(const float4*)(Ap + k0);
        float4 b = *(const float4*)(Bp + k0);
        As[lc + 0][lr] = a.x; As[lc + 1][lr] = a.y; As[lc + 2][lr] = a.z; As[lc + 3][lr] = a.w;
        Bs[lc + 0][lr] = b.x; Bs[lc + 1][lr] = b.y; Bs[lc + 2][lr] = b.z; Bs[lc + 3][lr] = b.w;
        __syncthreads();
#pragma unroll
        for (int kk = 0; kk < 16; kk++) {
            float4 av = *(const float4*)&As[kk][ty * 4];
            float4 bv = *(const float4*)&Bs[kk][tx * 4];
            float ar[4] = {av.x, av.y, av.z, av.w};
            float br[4] = {bv.x, bv.y, bv.z, bv.w};
#pragma unroll
            for (int i = 0; i < 4; i++)
#pragma unroll
                for (int j = 0; j < 4; j++) acc[i][j] += ar[i] * br[j];
        }
        __syncthreads();
    }
    float b0 = bias[n0 + tx * 4 + 0];
    float b1 = bias[n0 + tx * 4 + 1];
    float b2 = bias[n0 + tx * 4 + 2];
    float b3 = bias[n0 + tx * 4 + 3];
#pragma unroll
    for (int i = 0; i < 4; i++) {
        float4 v;
        v.x = acc[i][0] + b0; v.y = acc[i][1] + b1;
        v.z = acc[i][2] + b2; v.w = acc[i][3] + b3;
        if (RELU) {
            v.x = fmaxf(v.x, 0.f); v.y = fmaxf(v.y, 0.f);
            v.z = fmaxf(v.z, 0.f); v.w = fmaxf(v.w, 0.f);
        }
        *(float4*)&C[(size_t)(m0 + ty * 4 + i) * N + n0 + tx * 4] = v;
    }
}

// ---------------- flash attention with multiply-mask semantics --------------
__global__ __launch_bounds__(256) void attn_kernel(
    const float* __restrict__ qkv, float* __restrict__ out) {
    __shared__ float Qs[64][64];   // [d][q]
    __shared__ float KPs[64][64];  // K as [d][k]; reused as P [q][k]
    __shared__ float Vs[64][64];   // [k][d]
    int tid = threadIdx.x, tx = tid & 15, ty = tid >> 4;
    int qt = blockIdx.x, bh = blockIdx.y;
    int b = bh >> 3, h = bh & 7;
    const float* base = qkv + (size_t)b * T_ * 1536 + h * 192;
    int q0 = qt * 64;
    int lr = tid >> 2;
    int c0 = (tid & 3) * 16;
    {
        const float* qp = base + (size_t)(q0 + lr) * 1536;
#pragma unroll
        for (int u = 0; u < 4; u++) {
            float4 v = *(const float4*)(qp + c0 + 4 * u);
            Qs[c0 + 4 * u + 0][lr] = v.x; Qs[c0 + 4 * u + 1][lr] = v.y;
            Qs[c0 + 4 * u + 2][lr] = v.z; Qs[c0 + 4 * u + 3][lr] = v.w;
        }
    }
    float m[4], l[4], o[4][4];
#pragma unroll
    for (int i = 0; i < 4; i++) {
        m[i] = -1e30f; l[i] = 0.f;
#pragma unroll
        for (int j = 0; j < 4; j++) o[i][j] = 0.f;
    }
    for (int kt = 0; kt < 16; kt++) {
        __syncthreads();
        {
            const float* kp = base + (size_t)(kt * 64 + lr) * 1536 + 64;
            const float* vp = base + (size_t)(kt * 64 + lr) * 1536 + 128;
#pragma unroll
            for (int u = 0; u < 4; u++) {
                float4 kv = *(const float4*)(kp + c0 + 4 * u);
                KPs[c0 + 4 * u + 0][lr] = kv.x; KPs[c0 + 4 * u + 1][lr] = kv.y;
                KPs[c0 + 4 * u + 2][lr] = kv.z; KPs[c0 + 4 * u + 3][lr] = kv.w;
                *(float4*)&Vs[lr][c0 + 4 * u] = *(const float4*)(vp + c0 + 4 * u);
            }
        }
        __syncthreads();
        float s[4][4] = {};
        bool any_unmasked = (kt * 64 <= q0 + 63);
        if (any_unmasked) {
#pragma unroll
            for (int kk = 0; kk < 64; kk++) {
                float4 av = *(const float4*)&Qs[kk][ty * 4];
                float4 bv = *(const float4*)&KPs[kk][tx * 4];
                float ar[4] = {av.x, av.y, av.z, av.w};
                float br[4] = {bv.x, bv.y, bv.z, bv.w};
#pragma unroll
                for (int i = 0; i < 4; i++)
#pragma unroll
                    for (int j = 0; j < 4; j++) s[i][j] += ar[i] * br[j];
            }
        }
        float p[4][4];
#pragma unroll
        for (int i = 0; i < 4; i++) {
            int qpos = q0 + ty * 4 + i;
            float mt = -1e30f;
#pragma unroll
            for (int j = 0; j < 4; j++) {
                int kpos = kt * 64 + tx * 4 + j;
                float sv = (kpos <= qpos) ? s[i][j] * 0.125f : 0.f;
                s[i][j] = sv;
                mt = fmaxf(mt, sv);
            }
#pragma unroll
            for (int ofs = 1; ofs < 16; ofs <<= 1)
                mt = fmaxf(mt, __shfl_xor_sync(0xffffffffu, mt, ofs));
            float mn = fmaxf(m[i], mt);
            float alpha = __expf(m[i] - mn);
            m[i] = mn;
            float ps = 0.f;
#pragma unroll
            for (int j = 0; j < 4; j++) {
                p[i][j] = __expf(s[i][j] - mn);
                ps += p[i][j];
            }
#pragma unroll
            for (int ofs = 1; ofs < 16; ofs <<= 1)
                ps += __shfl_xor_sync(0xffffffffu, ps, ofs);
            l[i] = l[i] * alpha + ps;
#pragma unroll
            for (int j = 0; j < 4; j++) o[i][j] *= alpha;
        }
        __syncthreads();
#pragma unroll
        for (int i = 0; i < 4; i++)
            *(float4*)&KPs[ty * 4 + i][tx * 4] =
                make_float4(p[i][0], p[i][1], p[i][2], p[i][3]);
        __syncthreads();
#pragma unroll
        for (int kk = 0; kk < 64; kk++) {
            float a0 = KPs[ty * 4 + 0][kk];
            float a1 = KPs[ty * 4 + 1][kk];
            float a2 = KPs[ty * 4 + 2][kk];
            float a3 = KPs[ty * 4 + 3][kk];
            float4 bv = *(const float4*)&Vs[kk][tx * 4];
            float br[4] = {bv.x, bv.y, bv.z, bv.w};
#pragma unroll
            for (int j = 0; j < 4; j++) {
                o[0][j] += a0 * br[j]; o[1][j] += a1 * br[j];
                o[2][j] += a2 * br[j]; o[3][j] += a3 * br[j];
            }
        }
    }
    float* op = out + (size_t)(b * T_ + q0) * E_ + h * 64;
#pragma unroll
    for (int i = 0; i < 4; i++) {
        float inv = 1.f / l[i];
        *(float4*)(op + (size_t)(ty * 4 + i) * E_ + tx * 4) =
            make_float4(o[i][0] * inv, o[i][1] * inv, o[i][2] * inv, o[i][3] * inv);
    }
}

// ---------------- fused residual-add + layernorm ----------------------------
__global__ __launch_bounds__(128) void add_ln_kernel(
    const float* __restrict__ A, const float* __restrict__ R,
    const float* __restrict__ sc, const float* __restrict__ bi,
    float* __restrict__ out) {
    __shared__ float red[4], red2[4];
    int t = blockIdx.x, tid = threadIdx.x;
    int e0 = tid * 4;
    float4 a = *(const float4*)&A[(size_t)t * E_ + e0];
    float4 r = *(const float4*)&R[(size_t)t * E_ + e0];
    float v0 = a.x + r.x, v1 = a.y + r.y, v2 = a.z + r.z, v3 = a.w + r.w;
    float sum = v0 + v1 + v2 + v3;
#pragma unroll
    for (int o = 16; o; o >>= 1) sum += __shfl_xor_sync(0xffffffffu, sum, o);
    int w = tid >> 5, lane = tid & 31;
    if (lane == 0) red[w] = sum;
    __syncthreads();
    sum = red[0] + red[1] + red[2] + red[3];
    float mu = sum * (1.f / E_);
    float d0 = v0 - mu, d1 = v1 - mu, d2 = v2 - mu, d3 = v3 - mu;
    float sq = d0 * d0 + d1 * d1 + d2 * d2 + d3 * d3;
#pragma unroll
    for (int o = 16; o; o >>= 1) sq += __shfl_xor_sync(0xffffffffu, sq, o);
    if (lane == 0) red2[w] = sq;
    __syncthreads();
    sq = red2[0] + red2[1] + red2[2] + red2[3];
    float rstd = rsqrtf(sq * (1.f / E_) + 1e-5f);
    float4 s4 = *(const float4*)&sc[e0];
    float4 b4 = *(const float4*)&bi[e0];
    float4 o4;
    o4.x = d0 * rstd * s4.x + b4.x;
    o4.y = d1 * rstd * s4.y + b4.y;
    o4.z = d2 * rstd * s4.z + b4.z;
    o4.w = d3 * rstd * s4.w + b4.w;
    *(float4*)&out[(size_t)t * E_ + e0] = o4;
}

// ---------------- loss ------------------------------------------------------
__global__ void zero_loss(float* p) { *p = 0.f; }

__global__ __launch_bounds__(256) void loss_kernel(
    const float* __restrict__ logits, const int* __restrict__ tgt,
    float* __restrict__ loss_out) {
    int warp = threadIdx.x >> 5, lane = threadIdx.x & 31;
    int t = blockIdx.x * 8 + warp;
    const float* lp = logits + (size_t)t * V_;
    float x[4];
    float mx = -1e30f, tot = 0.f;
#pragma unroll
    for (int i = 0; i < 4; i++) {
        x[i] = lp[lane + 32 * i];
        mx = fmaxf(mx, x[i]);
        tot += x[i];
    }
#pragma unroll
    for (int o = 16; o; o >>= 1) mx = fmaxf(mx, __shfl_xor_sync(0xffffffffu, mx, o));
    float s = 0.f;
#pragma unroll
    for (int i = 0; i < 4; i++) s += expf(x[i] - mx);
#pragma unroll
    for (int o = 16; o; o >>= 1) {
        s += __shfl_xor_sync(0xffffffffu, s, o);
        tot += __shfl_xor_sync(0xffffffffu, tot, o);
    }
    if (lane == 0) {
        float logZ = mx + logf(s);
        int tv = g_is64[1] ? tgt[2 * t] : tgt[t];
        float nll = logZ - lp[tv];
        float smooth = logZ - tot * (1.f / V_);
        atomicAdd(loss_out, ((1.f - EPS_) * nll + EPS_ * smooth) * (1.f / BT));
    }
}

// ---------------- driver -----------------------------------------------------
extern "C" void kernel_launch(void* const* d_in, const int* in_sizes, int n_in,
                              void* d_out, int out_size) {
    const int*   inputs  = (const int*)d_in[0];
    const int*   targets = (const int*)d_in[1];
    const float* emb     = (const float*)d_in[2];
    const float* qkv_w   = (const float*)d_in[3];
    const float* qkv_b   = (const float*)d_in[4];
    const float* aff1_w  = (const float*)d_in[5];
    const float* aff1_b  = (const float*)d_in[6];
    const float* aff2_w  = (const float*)d_in[7];
    const float* aff2_b  = (const float*)d_in[8];
    const float* ffn1_w  = (const float*)d_in[9];
    const float* ffn1_b  = (const float*)d_in[10];
    const float* ffn2_w  = (const float*)d_in[11];
    const float* ffn2_b  = (const float*)d_in[12];
    const float* ln1_s   = (const float*)d_in[13];
    const float* ln1_b   = (const float*)d_in[14];
    const float* ln2_s   = (const float*)d_in[15];
    const float* ln2_b   = (const float*)d_in[16];
    const float* head_w  = (const float*)d_in[17];
    const float* head_b  = (const float*)d_in[18];
    float* out = (float*)d_out;

    float *px, *pqkv, *pa, *ph, *pb, *po1;
    cudaGetSymbolAddress((void**)&px,  g_x);
    cudaGetSymbolAddress((void**)&pqkv, g_qkv);
    cudaGetSymbolAddress((void**)&pa,  g_a);
    cudaGetSymbolAddress((void**)&ph,  g_h);
    cudaGetSymbolAddress((void**)&pb,  g_b2);
    cudaGetSymbolAddress((void**)&po1, g_o1);

    detect_kernel<<<1, 256>>>(inputs, BT, 0);
    detect_kernel<<<1, 256>>>(targets, BT, 1);
    embed_kernel<<<BT, 128>>>(inputs, emb);

    for (int l = 0; l < L_; l++) {
        sgemm128<0><<<dim3(12, 32), 256>>>(px, qkv_w + (size_t)l * 1536 * 512,
                                           qkv_b + (size_t)l * 1536, pqkv, 1536, 512);
        attn_kernel<<<dim3(16, 32), 256>>>(pqkv, pa);
        sgemm128<1><<<dim3(4, 32), 256>>>(pa, aff1_w + (size_t)l * 512 * 512,
                                          aff1_b + (size_t)l * 512, ph, 512, 512);
        sgemm128<0><<<dim3(4, 32), 256>>>(ph, aff2_w + (size_t)l * 512 * 512,
                                          aff2_b + (size_t)l * 512, pb, 512, 512);
        add_ln_kernel<<<BT, 128>>>(pb, px, ln1_s + (size_t)l * 512,
                                   ln1_b + (size_t)l * 512, po1);
        sgemm128<1><<<dim3(4, 32), 256>>>(po1, ffn1_w + (size_t)l * 512 * 512,
                                          ffn1_b + (size_t)l * 512, ph, 512, 512);
        sgemm128<0><<<dim3(4, 32), 256>>>(ph, ffn2_w + (size_t)l * 512 * 512,
                                          ffn2_b + (size_t)l * 512, pb, 512, 512);
        add_ln_kernel<<<BT, 128>>>(po1, pb, ln2_s + (size_t)l * 512,
                                   ln2_b + (size_t)l * 512, px);
    }

    float* logits_dst = (out_size >= BT * V_) ? out : pqkv;
    sgemm_nt<0><<<dim3(2, 64), 256>>>(px, head_w, head_b, logits_dst, V_, 512);

    float* loss_dst = nullptr;
    if (out_size > BT * V_) loss_dst = out + BT * V_;
    else if (out_size < BT * V_ && out_size >= 1) loss_dst = out;
    if (loss_dst) {
        zero_loss<<<1, 1>>>(loss_dst);
        loss_kernel<<<BT / 8, 256>>>(logits_dst, targets, loss_dst);
    }
}

// round 8
// speedup vs baseline: 1.7587x; 1.5243x over previous
#include <cuda_runtime.h>
#include <cuda_bf16.h>
#include <cstdint>

#define BT 4096
#define T_ 1024
#define E_ 512
#define H_ 8
#define L_ 8
#define V_ 128
#define EPS_ 0.1f
#define KB3 1536  // 3*E_ split-bf16 K dimension

// ---------------- scratch (device globals; no allocations allowed) ----------
__device__ float g_x[BT * E_];
__device__ float g_qkv[BT * 3 * E_];
__device__ float g_a[BT * E_];
__device__ float g_h[BT * E_];
__device__ float g_b2[BT * E_];
__device__ float g_o1[BT * E_];
__device__ int   g_is64[2];

__device__ __nv_bfloat16 g_abig[BT * KB3];
__device__ __nv_bfloat16 g_wqkv[L_ * 1536 * KB3];
__device__ __nv_bfloat16 g_w1[L_ * 512 * KB3];
__device__ __nv_bfloat16 g_w2[L_ * 512 * KB3];
__device__ __nv_bfloat16 g_w3[L_ * 512 * KB3];
__device__ __nv_bfloat16 g_w4[L_ * 512 * KB3];

// ---------------- PTX helpers ------------------------------------------------
#define SW128(o) ((o) ^ (((o) >> 3) & 0x70))
#define CP_ASYNC16(dst, src) \
    asm volatile("cp.async.cg.shared.global [%0], [%1], 16;" :: "r"(dst), "l"(src))
#define CP_COMMIT() asm volatile("cp.async.commit_group;" ::: "memory")
#define CP_WAIT1() asm volatile("cp.async.wait_group 1;" ::: "memory")
#define CP_WAIT0() asm volatile("cp.async.wait_group 0;" ::: "memory")

#define LDMATRIX_X4(r0, r1, r2, r3, addr)                                      \
    asm volatile("ldmatrix.sync.aligned.m8n8.x4.shared.b16 {%0,%1,%2,%3}, [%4];" \
                 : "=r"(r0), "=r"(r1), "=r"(r2), "=r"(r3) : "r"(addr))

#define MMA16816(d, a, b0, b1)                                                 \
    asm volatile("mma.sync.aligned.m16n8k16.row.col.f32.bf16.bf16.f32 "        \
                 "{%0,%1,%2,%3}, {%4,%5,%6,%7}, {%8,%9}, {%0,%1,%2,%3};"       \
                 : "+f"((d)[0]), "+f"((d)[1]), "+f"((d)[2]), "+f"((d)[3])      \
                 : "r"((a)[0]), "r"((a)[1]), "r"((a)[2]), "r"((a)[3]),         \
                   "r"(b0), "r"(b1))

// ---------------- split-bf16 conversion -------------------------------------
// APAT=1: [hi|lo|hi] (activations)   APAT=0: [hi|hi|lo] (weights)
template <int APAT>
__global__ __launch_bounds__(128) void conv_split(
    const float* __restrict__ X, __nv_bfloat16* __restrict__ O) {
    size_t r = blockIdx.x;
    int c = threadIdx.x * 4;
    float4 v = *(const float4*)&X[r * 512 + c];
    float f[4] = {v.x, v.y, v.z, v.w};
    __nv_bfloat16 h[4], lo[4];
#pragma unroll
    for (int i = 0; i < 4; i++) {
        h[i] = __float2bfloat16(f[i]);
        lo[i] = __float2bfloat16(f[i] - __bfloat162float(h[i]));
    }
    __nv_bfloat16* o = O + r * KB3 + c;
    __nv_bfloat162 h01, h23, l01, l23;
    h01.x = h[0]; h01.y = h[1]; h23.x = h[2]; h23.y = h[3];
    l01.x = lo[0]; l01.y = lo[1]; l23.x = lo[2]; l23.y = lo[3];
    *(__nv_bfloat162*)&o[0] = h01;
    *(__nv_bfloat162*)&o[2] = h23;
    *(__nv_bfloat162*)&o[512] = APAT ? l01 : h01;
    *(__nv_bfloat162*)&o[514] = APAT ? l23 : h23;
    *(__nv_bfloat162*)&o[1024] = APAT ? h01 : l01;
    *(__nv_bfloat162*)&o[1026] = APAT ? h23 : l23;
}

// ---------------- mma.sync GEMM: C[M,N] = A'[M,1536]*B'[N,1536]^T + bias ----
// 128x128 CTA tile, BK=64 bf16, 3-stage cp.async pipeline, 8 warps (4m x 2n),
// warp tile 32x64 via m16n8k16 HMMA. A,B K-major, SW128-swizzled smem.
#define STAGE_BYTES 32768            // A 16KB + B 16KB
#define SMEM_MMA (3 * STAGE_BYTES)   // 96 KB
#define NCHUNK 24                    // 1536 / 64

__device__ __forceinline__ void mma_load_chunk(
    uint32_t sbase, int stage,
    const __nv_bfloat16* A, const __nv_bfloat16* Bw,
    int m0, int n0, int c, int tid) {
    uint32_t abase = sbase + stage * STAGE_BYTES;
    uint32_t bbase = abase + 16384;
#pragma unroll
    for (int i = 0; i < 4; i++) {
        int g = i * 256 + tid, row = g >> 3, seg = g & 7;
        uint32_t dst = abase + SW128(row * 128 + seg * 16);
        const char* src = (const char*)A + (size_t)(m0 + row) * 3072 + c * 128 + seg * 16;
        CP_ASYNC16(dst, src);
    }
#pragma unroll
    for (int i = 0; i < 4; i++) {
        int g = i * 256 + tid, row = g >> 3, seg = g & 7;
        uint32_t dst = bbase + SW128(row * 128 + seg * 16);
        const char* src = (const char*)Bw + (size_t)(n0 + row) * 3072 + c * 128 + seg * 16;
        CP_ASYNC16(dst, src);
    }
    CP_COMMIT();
}

template <int RELU>
__global__ __launch_bounds__(256) void gemm_mma(
    const __nv_bfloat16* __restrict__ A, const __nv_bfloat16* __restrict__ Bw,
    const float* __restrict__ bias, float* __restrict__ C, int N) {
    extern __shared__ char smem[];
    uint32_t sbase = (uint32_t)__cvta_generic_to_shared(smem);
    int tid = threadIdx.x, wid = tid >> 5, lane = tid & 31;
    int m0 = blockIdx.y * 128, n0 = blockIdx.x * 128;
    int warp_m = wid & 3, warp_n = wid >> 2;

    float acc[2][8][4];
#pragma unroll
    for (int mt = 0; mt < 2; mt++)
#pragma unroll
        for (int nt = 0; nt < 8; nt++)
#pragma unroll
            for (int e = 0; e < 4; e++) acc[mt][nt][e] = 0.f;

    mma_load_chunk(sbase, 0, A, Bw, m0, n0, 0, tid);
    mma_load_chunk(sbase, 1, A, Bw, m0, n0, 1, tid);

    // precomputed fragment addresses (stage-relative)
    int a_row = warp_m * 32 + (lane & 15);
    int a_col8 = (lane >> 4) << 3;
    int bq = lane >> 3, br = lane & 7;
    int b_n = warp_n * 64 + ((bq >> 1) << 3) + br;
    int b_col8 = (bq & 1) << 3;

    for (int c = 0; c < NCHUNK; c++) {
        if (c + 1 < NCHUNK) { CP_WAIT1(); } else { CP_WAIT0(); }
        __syncthreads();
        if (c + 2 < NCHUNK)
            mma_load_chunk(sbase, (c + 2) % 3, A, Bw, m0, n0, c + 2, tid);

        uint32_t abase = sbase + (c % 3) * STAGE_BYTES;
        uint32_t bbase = abase + 16384;
#pragma unroll
        for (int ks = 0; ks < 4; ks++) {
            uint32_t af[2][4];
#pragma unroll
            for (int mt = 0; mt < 2; mt++) {
                uint32_t off = (uint32_t)((a_row + mt * 16) * 128 + (ks * 16 + a_col8) * 2);
                LDMATRIX_X4(af[mt][0], af[mt][1], af[mt][2], af[mt][3],
                            abase + SW128(off));
            }
#pragma unroll
            for (int np = 0; np < 4; np++) {
                uint32_t bf[4];
                uint32_t off = (uint32_t)((b_n + np * 16) * 128 + (ks * 16 + b_col8) * 2);
                LDMATRIX_X4(bf[0], bf[1], bf[2], bf[3], bbase + SW128(off));
#pragma unroll
                for (int mt = 0; mt < 2; mt++) {
                    MMA16816(acc[mt][2 * np], af[mt], bf[0], bf[1]);
                    MMA16816(acc[mt][2 * np + 1], af[mt], bf[2], bf[3]);
                }
            }
        }
    }

    // epilogue: direct fp32 stores with bias (+ReLU)
    int g = lane >> 2, q = lane & 3;
#pragma unroll
    for (int mt = 0; mt < 2; mt++) {
        int row0 = m0 + warp_m * 32 + mt * 16 + g;
#pragma unroll
        for (int nt = 0; nt < 8; nt++) {
            int col = n0 + warp_n * 64 + nt * 8 + q * 2;
            float b0 = bias[col], b1 = bias[col + 1];
            float v0 = acc[mt][nt][0] + b0, v1 = acc[mt][nt][1] + b1;
            float v2 = acc[mt][nt][2] + b0, v3 = acc[mt][nt][3] + b1;
            if (RELU) {
                v0 = fmaxf(v0, 0.f); v1 = fmaxf(v1, 0.f);
                v2 = fmaxf(v2, 0.f); v3 = fmaxf(v3, 0.f);
            }
            *(float2*)&C[(size_t)row0 * N + col] = make_float2(v0, v1);
            *(float2*)&C[(size_t)(row0 + 8) * N + col] = make_float2(v2, v3);
        }
    }
}

// ---------------- int64-vs-int32 detection ----------------------------------
__global__ void detect_kernel(const int* __restrict__ p, int n, int slot) {
    __shared__ int red[256];
    int acc = 0;
    for (int j = 2 * threadIdx.x + 1; j < n; j += 512) acc |= p[j];
    red[threadIdx.x] = acc;
    __syncthreads();
    for (int s = 128; s > 0; s >>= 1) {
        if (threadIdx.x < s) red[threadIdx.x] |= red[threadIdx.x + s];
        __syncthreads();
    }
    if (threadIdx.x == 0) g_is64[slot] = (red[0] == 0) ? 1 : 0;
}

// ---------------- embedding gather ------------------------------------------
__global__ void embed_kernel(const int* __restrict__ inp, const float* __restrict__ emb) {
    int t = blockIdx.x;
    int tok = g_is64[0] ? inp[2 * t] : inp[t];
    const float4* src = (const float4*)(emb + (size_t)tok * E_);
    float4* dst = (float4*)(g_x + (size_t)t * E_);
    for (int i = threadIdx.x; i < E_ / 4; i += blockDim.x) dst[i] = src[i];
}

// ---------------- small SGEMM (head, N=128): 64x64x16 tile ------------------
template <int RELU>
__global__ __launch_bounds__(256) void sgemm_nt(
    const float* __restrict__ A, const float* __restrict__ B,
    const float* __restrict__ bias, float* __restrict__ C, int N, int K) {
    __shared__ float As[16][64];
    __shared__ float Bs[16][64];
    int tid = threadIdx.x;
    int tx = tid & 15, ty = tid >> 4;
    int m0 = blockIdx.y * 64, n0 = blockIdx.x * 64;
    int lr = tid >> 2;
    int lc = (tid & 3) * 4;
    const float* Ap = A + (size_t)(m0 + lr) * K + lc;
    const float* Bp = B + (size_t)(n0 + lr) * K + lc;
    float acc[4][4] = {};
    for (int k0 = 0; k0 < K; k0 += 16) {
        float4 a = *(const float4*)(Ap + k0);
        float4 b = *(const float4*)(Bp + k0);
        As[lc + 0][lr] = a.x; As[lc + 1][lr] = a.y; As[lc + 2][lr] = a.z; As[lc + 3][lr] = a.w;
        Bs[lc + 0][lr] = b.x; Bs[lc + 1][lr] = b.y; Bs[lc + 2][lr] = b.z; Bs[lc + 3][lr] = b.w;
        __syncthreads();
#pragma unroll
        for (int kk = 0; kk < 16; kk++) {
            float4 av = *(const float4*)&As[kk][ty * 4];
            float4 bv = *(const float4*)&Bs[kk][tx * 4];
            float ar[4] = {av.x, av.y, av.z, av.w};
            float br[4] = {bv.x, bv.y, bv.z, bv.w};
#pragma unroll
            for (int i = 0; i < 4; i++)
#pragma unroll
                for (int j = 0; j < 4; j++) acc[i][j] += ar[i] * br[j];
        }
        __syncthreads();
    }
    float b0 = bias[n0 + tx * 4 + 0];
    float b1 = bias[n0 + tx * 4 + 1];
    float b2 = bias[n0 + tx * 4 + 2];
    float b3 = bias[n0 + tx * 4 + 3];
#pragma unroll
    for (int i = 0; i < 4; i++) {
        float4 v;
        v.x = acc[i][0] + b0; v.y = acc[i][1] + b1;
        v.z = acc[i][2] + b2; v.w = acc[i][3] + b3;
        if (RELU) {
            v.x = fmaxf(v.x, 0.f); v.y = fmaxf(v.y, 0.f);
            v.z = fmaxf(v.z, 0.f); v.w = fmaxf(v.w, 0.f);
        }
        *(float4*)&C[(size_t)(m0 + ty * 4 + i) * N + n0 + tx * 4] = v;
    }
}

// ---------------- flash attention with multiply-mask semantics --------------
__global__ __launch_bounds__(256) void attn_kernel(
    const float* __restrict__ qkv, float* __restrict__ out) {
    __shared__ float Qs[64][64];
    __shared__ float KPs[64][64];
    __shared__ float Vs[64][64];
    int tid = threadIdx.x, tx = tid & 15, ty = tid >> 4;
    int qt = blockIdx.x, bh = blockIdx.y;
    int b = bh >> 3, h = bh & 7;
    const float* base = qkv + (size_t)b * T_ * 1536 + h * 192;
    int q0 = qt * 64;
    int lr = tid >> 2;
    int c0 = (tid & 3) * 16;
    {
        const float* qp = base + (size_t)(q0 + lr) * 1536;
#pragma unroll
        for (int u = 0; u < 4; u++) {
            float4 v = *(const float4*)(qp + c0 + 4 * u);
            Qs[c0 + 4 * u + 0][lr] = v.x; Qs[c0 + 4 * u + 1][lr] = v.y;
            Qs[c0 + 4 * u + 2][lr] = v.z; Qs[c0 + 4 * u + 3][lr] = v.w;
        }
    }
    float m[4], l[4], o[4][4];
#pragma unroll
    for (int i = 0; i < 4; i++) {
        m[i] = -1e30f; l[i] = 0.f;
#pragma unroll
        for (int j = 0; j < 4; j++) o[i][j] = 0.f;
    }
    for (int kt = 0; kt < 16; kt++) {
        __syncthreads();
        {
            const float* kp = base + (size_t)(kt * 64 + lr) * 1536 + 64;
            const float* vp = base + (size_t)(kt * 64 + lr) * 1536 + 128;
#pragma unroll
            for (int u = 0; u < 4; u++) {
                float4 kv = *(const float4*)(kp + c0 + 4 * u);
                KPs[c0 + 4 * u + 0][lr] = kv.x; KPs[c0 + 4 * u + 1][lr] = kv.y;
                KPs[c0 + 4 * u + 2][lr] = kv.z; KPs[c0 + 4 * u + 3][lr] = kv.w;
                *(float4*)&Vs[lr][c0 + 4 * u] = *(const float4*)(vp + c0 + 4 * u);
            }
        }
        __syncthreads();
        float s[4][4] = {};
        bool any_unmasked = (kt * 64 <= q0 + 63);
        if (any_unmasked) {
#pragma unroll
            for (int kk = 0; kk < 64; kk++) {
                float4 av = *(const float4*)&Qs[kk][ty * 4];
                float4 bv = *(const float4*)&KPs[kk][tx * 4];
                float ar[4] = {av.x, av.y, av.z, av.w};
                float br[4] = {bv.x, bv.y, bv.z, bv.w};
#pragma unroll
                for (int i = 0; i < 4; i++)
#pragma unroll
                    for (int j = 0; j < 4; j++) s[i][j] += ar[i] * br[j];
            }
        }
        float p[4][4];
#pragma unroll
        for (int i = 0; i < 4; i++) {
            int qpos = q0 + ty * 4 + i;
            float mt = -1e30f;
#pragma unroll
            for (int j = 0; j < 4; j++) {
                int kpos = kt * 64 + tx * 4 + j;
                float sv = (kpos <= qpos) ? s[i][j] * 0.125f : 0.f;
                s[i][j] = sv;
                mt = fmaxf(mt, sv);
            }
#pragma unroll
            for (int ofs = 1; ofs < 16; ofs <<= 1)
                mt = fmaxf(mt, __shfl_xor_sync(0xffffffffu, mt, ofs));
            float mn = fmaxf(m[i], mt);
            float alpha = __expf(m[i] - mn);
            m[i] = mn;
            float ps = 0.f;
#pragma unroll
            for (int j = 0; j < 4; j++) {
                p[i][j] = __expf(s[i][j] - mn);
                ps += p[i][j];
            }
#pragma unroll
            for (int ofs = 1; ofs < 16; ofs <<= 1)
                ps += __shfl_xor_sync(0xffffffffu, ps, ofs);
            l[i] = l[i] * alpha + ps;
#pragma unroll
            for (int j = 0; j < 4; j++) o[i][j] *= alpha;
        }
        __syncthreads();
#pragma unroll
        for (int i = 0; i < 4; i++)
            *(float4*)&KPs[ty * 4 + i][tx * 4] =
                make_float4(p[i][0], p[i][1], p[i][2], p[i][3]);
        __syncthreads();
#pragma unroll
        for (int kk = 0; kk < 64; kk++) {
            float a0 = KPs[ty * 4 + 0][kk];
            float a1 = KPs[ty * 4 + 1][kk];
            float a2 = KPs[ty * 4 + 2][kk];
            float a3 = KPs[ty * 4 + 3][kk];
            float4 bv = *(const float4*)&Vs[kk][tx * 4];
            float br[4] = {bv.x, bv.y, bv.z, bv.w};
#pragma unroll
            for (int j = 0; j < 4; j++) {
                o[0][j] += a0 * br[j]; o[1][j] += a1 * br[j];
                o[2][j] += a2 * br[j]; o[3][j] += a3 * br[j];
            }
        }
    }
    float* op = out + (size_t)(b * T_ + q0) * E_ + h * 64;
#pragma unroll
    for (int i = 0; i < 4; i++) {
        float inv = 1.f / l[i];
        *(float4*)(op + (size_t)(ty * 4 + i) * E_ + tx * 4) =
            make_float4(o[i][0] * inv, o[i][1] * inv, o[i][2] * inv, o[i][3] * inv);
    }
}

// ---------------- fused residual-add + layernorm ----------------------------
__global__ __launch_bounds__(128) void add_ln_kernel(
    const float* __restrict__ A, const float* __restrict__ R,
    const float* __restrict__ sc, const float* __restrict__ bi,
    float* __restrict__ out) {
    __shared__ float red[4], red2[4];
    int t = blockIdx.x, tid = threadIdx.x;
    int e0 = tid * 4;
    float4 a = *(const float4*)&A[(size_t)t * E_ + e0];
    float4 r = *(const float4*)&R[(size_t)t * E_ + e0];
    float v0 = a.x + r.x, v1 = a.y + r.y, v2 = a.z + r.z, v3 = a.w + r.w;
    float sum = v0 + v1 + v2 + v3;
#pragma unroll
    for (int o = 16; o; o >>= 1) sum += __shfl_xor_sync(0xffffffffu, sum, o);
    int w = tid >> 5, lane = tid & 31;
    if (lane == 0) red[w] = sum;
    __syncthreads();
    sum = red[0] + red[1] + red[2] + red[3];
    float mu = sum * (1.f / E_);
    float d0 = v0 - mu, d1 = v1 - mu, d2 = v2 - mu, d3 = v3 - mu;
    float sq = d0 * d0 + d1 * d1 + d2 * d2 + d3 * d3;
#pragma unroll
    for (int o = 16; o; o >>= 1) sq += __shfl_xor_sync(0xffffffffu, sq, o);
    if (lane == 0) red2[w] = sq;
    __syncthreads();
    sq = red2[0] + red2[1] + red2[2] + red2[3];
    float rstd = rsqrtf(sq * (1.f / E_) + 1e-5f);
    float4 s4 = *(const float4*)&sc[e0];
    float4 b4 = *(const float4*)&bi[e0];
    float4 o4;
    o4.x = d0 * rstd * s4.x + b4.x;
    o4.y = d1 * rstd * s4.y + b4.y;
    o4.z = d2 * rstd * s4.z + b4.z;
    o4.w = d3 * rstd * s4.w + b4.w;
    *(float4*)&out[(size_t)t * E_ + e0] = o4;
}

// ---------------- loss ------------------------------------------------------
__global__ void zero_loss(float* p) { *p = 0.f; }

__global__ __launch_bounds__(256) void loss_kernel(
    const float* __restrict__ logits, const int* __restrict__ tgt,
    float* __restrict__ loss_out) {
    int warp = threadIdx.x >> 5, lane = threadIdx.x & 31;
    int t = blockIdx.x * 8 + warp;
    const float* lp = logits + (size_t)t * V_;
    float x[4];
    float mx = -1e30f, tot = 0.f;
#pragma unroll
    for (int i = 0; i < 4; i++) {
        x[i] = lp[lane + 32 * i];
        mx = fmaxf(mx, x[i]);
        tot += x[i];
    }
#pragma unroll
    for (int o = 16; o; o >>= 1) mx = fmaxf(mx, __shfl_xor_sync(0xffffffffu, mx, o));
    float s = 0.f;
#pragma unroll
    for (int i = 0; i < 4; i++) s += expf(x[i] - mx);
#pragma unroll
    for (int o = 16; o; o >>= 1) {
        s += __shfl_xor_sync(0xffffffffu, s, o);
        tot += __shfl_xor_sync(0xffffffffu, tot, o);
    }
    if (lane == 0) {
        float logZ = mx + logf(s);
        int tv = g_is64[1] ? tgt[2 * t] : tgt[t];
        float nll = logZ - lp[tv];
        float smooth = logZ - tot * (1.f / V_);
        atomicAdd(loss_out, ((1.f - EPS_) * nll + EPS_ * smooth) * (1.f / BT));
    }
}

// ---------------- driver -----------------------------------------------------
extern "C" void kernel_launch(void* const* d_in, const int* in_sizes, int n_in,
                              void* d_out, int out_size) {
    const int*   inputs  = (const int*)d_in[0];
    const int*   targets = (const int*)d_in[1];
    const float* emb     = (const float*)d_in[2];
    const float* qkv_w   = (const float*)d_in[3];
    const float* qkv_b   = (const float*)d_in[4];
    const float* aff1_w  = (const float*)d_in[5];
    const float* aff1_b  = (const float*)d_in[6];
    const float* aff2_w  = (const float*)d_in[7];
    const float* aff2_b  = (const float*)d_in[8];
    const float* ffn1_w  = (const float*)d_in[9];
    const float* ffn1_b  = (const float*)d_in[10];
    const float* ffn2_w  = (const float*)d_in[11];
    const float* ffn2_b  = (const float*)d_in[12];
    const float* ln1_s   = (const float*)d_in[13];
    const float* ln1_b   = (const float*)d_in[14];
    const float* ln2_s   = (const float*)d_in[15];
    const float* ln2_b   = (const float*)d_in[16];
    const float* head_w  = (const float*)d_in[17];
    const float* head_b  = (const float*)d_in[18];
    float* out = (float*)d_out;

    cudaFuncSetAttribute(gemm_mma<0>, cudaFuncAttributeMaxDynamicSharedMemorySize, SMEM_MMA);
    cudaFuncSetAttribute(gemm_mma<1>, cudaFuncAttributeMaxDynamicSharedMemorySize, SMEM_MMA);

    float *px, *pqkv, *pa, *ph, *pb, *po1;
    __nv_bfloat16 *pab, *pwqkv, *pw1, *pw2, *pw3, *pw4;
    cudaGetSymbolAddress((void**)&px,   g_x);
    cudaGetSymbolAddress((void**)&pqkv, g_qkv);
    cudaGetSymbolAddress((void**)&pa,   g_a);
    cudaGetSymbolAddress((void**)&ph,   g_h);
    cudaGetSymbolAddress((void**)&pb,   g_b2);
    cudaGetSymbolAddress((void**)&po1,  g_o1);
    cudaGetSymbolAddress((void**)&pab,  g_abig);
    cudaGetSymbolAddress((void**)&pwqkv, g_wqkv);
    cudaGetSymbolAddress((void**)&pw1,  g_w1);
    cudaGetSymbolAddress((void**)&pw2,  g_w2);
    cudaGetSymbolAddress((void**)&pw3,  g_w3);
    cudaGetSymbolAddress((void**)&pw4,  g_w4);

    detect_kernel<<<1, 256>>>(inputs, BT, 0);
    detect_kernel<<<1, 256>>>(targets, BT, 1);
    embed_kernel<<<BT, 128>>>(inputs, emb);

    // split all weights once per launch
    conv_split<0><<<L_ * 1536, 128>>>(qkv_w,  pwqkv);
    conv_split<0><<<L_ * 512, 128>>>(aff1_w, pw1);
    conv_split<0><<<L_ * 512, 128>>>(aff2_w, pw2);
    conv_split<0><<<L_ * 512, 128>>>(ffn1_w, pw3);
    conv_split<0><<<L_ * 512, 128>>>(ffn2_w, pw4);

    for (int l = 0; l < L_; l++) {
        conv_split<1><<<BT, 128>>>(px, pab);
        gemm_mma<0><<<dim3(12, 32), 256, SMEM_MMA>>>(
            pab, pwqkv + (size_t)l * 1536 * KB3, qkv_b + (size_t)l * 1536, pqkv, 1536);
        attn_kernel<<<dim3(16, 32), 256>>>(pqkv, pa);
        conv_split<1><<<BT, 128>>>(pa, pab);
        gemm_mma<1><<<dim3(4, 32), 256, SMEM_MMA>>>(
            pab, pw1 + (size_t)l * 512 * KB3, aff1_b + (size_t)l * 512, ph, 512);
        conv_split<1><<<BT, 128>>>(ph, pab);
        gemm_mma<0><<<dim3(4, 32), 256, SMEM_MMA>>>(
            pab, pw2 + (size_t)l * 512 * KB3, aff2_b + (size_t)l * 512, pb, 512);
        add_ln_kernel<<<BT, 128>>>(pb, px, ln1_s + (size_t)l * 512,
                                   ln1_b + (size_t)l * 512, po1);
        conv_split<1><<<BT, 128>>>(po1, pab);
        gemm_mma<1><<<dim3(4, 32), 256, SMEM_MMA>>>(
            pab, pw3 + (size_t)l * 512 * KB3, ffn1_b + (size_t)l * 512, ph, 512);
        conv_split<1><<<BT, 128>>>(ph, pab);
        gemm_mma<0><<<dim3(4, 32), 256, SMEM_MMA>>>(
            pab, pw4 + (size_t)l * 512 * KB3, ffn2_b + (size_t)l * 512, pb, 512);
        add_ln_kernel<<<BT, 128>>>(po1, pb, ln2_s + (size_t)l * 512,
                                   ln2_b + (size_t)l * 512, px);
    }

    float* logits_dst = (out_size >= BT * V_) ? out : pqkv;
    sgemm_nt<0><<<dim3(2, 64), 256>>>(px, head_w, head_b, logits_dst, V_, 512);

    float* loss_dst = nullptr;
    if (out_size > BT * V_) loss_dst = out + BT * V_;
    else if (out_size < BT * V_ && out_size >= 1) loss_dst = out;
    if (loss_dst) {
        zero_loss<<<1, 1>>>(loss_dst);
        loss_kernel<<<BT / 8, 256>>>(logits_dst, targets, loss_dst);
    }
}

// round 11
// speedup vs baseline: 2.4942x; 1.4182x over previous
#include <cuda_runtime.h>
#include <cuda_bf16.h>
#include <cstdint>

#define BT 4096
#define T_ 1024
#define E_ 512
#define H_ 8
#define L_ 8
#define V_ 128
#define EPS_ 0.1f
#define KB3 1536  // 3*E_ split-bf16 K dimension

// ---------------- scratch (device globals; no allocations allowed) ----------
__device__ float g_x[BT * E_];
__device__ float g_qkv[BT * 3 * E_];
__device__ float g_a[BT * E_];
__device__ float g_h[BT * E_];
__device__ float g_b2[BT * E_];
__device__ float g_o1[BT * E_];
__device__ int   g_is64[2];

__device__ __nv_bfloat16 g_abig[BT * KB3];
__device__ __nv_bfloat16 g_wqkv[L_ * 1536 * KB3];
__device__ __nv_bfloat16 g_w1[L_ * 512 * KB3];
__device__ __nv_bfloat16 g_w2[L_ * 512 * KB3];
__device__ __nv_bfloat16 g_w3[L_ * 512 * KB3];
__device__ __nv_bfloat16 g_w4[L_ * 512 * KB3];

// attention split planes: [(b*8+h)*1024 + t]*64 + d
__device__ __nv_bfloat16 g_qh[32 * 1024 * 64];
__device__ __nv_bfloat16 g_ql[32 * 1024 * 64];
__device__ __nv_bfloat16 g_kh[32 * 1024 * 64];
__device__ __nv_bfloat16 g_kl[32 * 1024 * 64];
__device__ __nv_bfloat16 g_vh[32 * 1024 * 64];
__device__ __nv_bfloat16 g_vl[32 * 1024 * 64];
__device__ float g_vsuf[32 * 17 * 64];  // V suffix sums per (bh, tile, d)

// ---------------- PTX helpers ------------------------------------------------
#define SW128(o) ((o) ^ (((o) >> 3) & 0x70))
#define CP_ASYNC16(dst, src) \
    asm volatile("cp.async.cg.shared.global [%0], [%1], 16;" :: "r"(dst), "l"(src))
#define CP_COMMIT() asm volatile("cp.async.commit_group;" ::: "memory")
#define CP_WAIT1() asm volatile("cp.async.wait_group 1;" ::: "memory")
#define CP_WAIT0() asm volatile("cp.async.wait_group 0;" ::: "memory")

#define LDMATRIX_X4(r0, r1, r2, r3, addr)                                      \
    asm volatile("ldmatrix.sync.aligned.m8n8.x4.shared.b16 {%0,%1,%2,%3}, [%4];" \
                 : "=r"(r0), "=r"(r1), "=r"(r2), "=r"(r3) : "r"(addr))

#define LDMATRIX_X4T(r0, r1, r2, r3, addr)                                     \
    asm volatile("ldmatrix.sync.aligned.m8n8.x4.trans.shared.b16 {%0,%1,%2,%3}, [%4];" \
                 : "=r"(r0), "=r"(r1), "=r"(r2), "=r"(r3) : "r"(addr))

#define MMA16816(d, a, b0, b1)                                                 \
    asm volatile("mma.sync.aligned.m16n8k16.row.col.f32.bf16.bf16.f32 "        \
                 "{%0,%1,%2,%3}, {%4,%5,%6,%7}, {%8,%9}, {%0,%1,%2,%3};"       \
                 : "+f"((d)[0]), "+f"((d)[1]), "+f"((d)[2]), "+f"((d)[3])      \
                 : "r"((a)[0]), "r"((a)[1]), "r"((a)[2]), "r"((a)[3]),         \
                   "r"(b0), "r"(b1))

__device__ __forceinline__ uint32_t pack_hi_res(float a, float b, float& ra, float& rb) {
    __nv_bfloat16 h0 = __float2bfloat16(a), h1 = __float2bfloat16(b);
    ra = a - __bfloat162float(h0);
    rb = b - __bfloat162float(h1);
    return ((uint32_t)__bfloat16_as_ushort(h1) << 16) | (uint32_t)__bfloat16_as_ushort(h0);
}
__device__ __forceinline__ uint32_t pack2bf(float a, float b) {
    __nv_bfloat162 t = __floats2bfloat162_rn(a, b);
    return *reinterpret_cast<uint32_t*>(&t);
}

// ---------------- split-bf16 conversion -------------------------------------
// APAT=1: [hi|lo|hi] (activations)   APAT=0: [hi|hi|lo] (weights)
template <int APAT>
__global__ __launch_bounds__(128) void conv_split(
    const float* __restrict__ X, __nv_bfloat16* __restrict__ O) {
    size_t r = blockIdx.x;
    int c = threadIdx.x * 4;
    float4 v = *(const float4*)&X[r * 512 + c];
    float f[4] = {v.x, v.y, v.z, v.w};
    __nv_bfloat16 h[4], lo[4];
#pragma unroll
    for (int i = 0; i < 4; i++) {
        h[i] = __float2bfloat16(f[i]);
        lo[i] = __float2bfloat16(f[i] - __bfloat162float(h[i]));
    }
    __nv_bfloat16* o = O + r * KB3 + c;
    __nv_bfloat162 h01, h23, l01, l23;
    h01.x = h[0]; h01.y = h[1]; h23.x = h[2]; h23.y = h[3];
    l01.x = lo[0]; l01.y = lo[1]; l23.x = lo[2]; l23.y = lo[3];
    *(__nv_bfloat162*)&o[0] = h01;
    *(__nv_bfloat162*)&o[2] = h23;
    *(__nv_bfloat162*)&o[512] = APAT ? l01 : h01;
    *(__nv_bfloat162*)&o[514] = APAT ? l23 : h23;
    *(__nv_bfloat162*)&o[1024] = APAT ? h01 : l01;
    *(__nv_bfloat162*)&o[1026] = APAT ? h23 : l23;
}

// ---------------- qkv fp32 -> attention split planes ------------------------
__global__ __launch_bounds__(64) void conv_qkv(
    const float* __restrict__ qkv,
    __nv_bfloat16* __restrict__ qh, __nv_bfloat16* __restrict__ ql,
    __nv_bfloat16* __restrict__ kh, __nv_bfloat16* __restrict__ kl,
    __nv_bfloat16* __restrict__ vh, __nv_bfloat16* __restrict__ vl) {
    int bt = blockIdx.x, h = blockIdx.y, d = threadIdx.x;
    int b = bt >> 10, t = bt & 1023;
    size_t src = (size_t)bt * 1536 + h * 192;
    size_t dst = ((size_t)(b * 8 + h) * 1024 + t) * 64 + d;
    float q = qkv[src + d], k = qkv[src + 64 + d], v = qkv[src + 128 + d];
    __nv_bfloat16 t1 = __float2bfloat16(q);
    qh[dst] = t1; ql[dst] = __float2bfloat16(q - __bfloat162float(t1));
    t1 = __float2bfloat16(k);
    kh[dst] = t1; kl[dst] = __float2bfloat16(k - __bfloat162float(t1));
    t1 = __float2bfloat16(v);
    vh[dst] = t1; vl[dst] = __float2bfloat16(v - __bfloat162float(t1));
}

// ---------------- V suffix sums ----------------------------------------------
__global__ __launch_bounds__(64) void vsuf_kernel(
    const float* __restrict__ qkv, float* __restrict__ vsuf) {
    int bh = blockIdx.x, d = threadIdx.x;
    int b = bh >> 3, h = bh & 7;
    float s = 0.f;
    vsuf[((size_t)bh * 17 + 16) * 64 + d] = 0.f;
    for (int jt = 15; jt >= 0; jt--) {
        const float* p = qkv + ((size_t)(b * 1024 + jt * 64)) * 1536 + h * 192 + 128 + d;
#pragma unroll 4
        for (int t = 0; t < 64; t++) s += p[(size_t)t * 1536];
        vsuf[((size_t)bh * 17 + jt) * 64 + d] = s;
    }
}

// ---------------- tensor-core flash attention --------------------------------
// multiply-mask semantics: masked scores are EXACTLY 0. Tiles kt<=qt computed;
// future (fully-masked) tiles contribute exp(0-m)*Vsuf in closed form.
#define ATT_SMEM 81920
#define AQH 0
#define AQL 8192
#define AST(s) (16384 + (s) * 32768)  // per stage: Kh 0, Kl 8K, Vh 16K, Vl 24K

__device__ __forceinline__ void att_load_kv(
    uint32_t sb, int stage, size_t base,
    const __nv_bfloat16* kh, const __nv_bfloat16* kl,
    const __nv_bfloat16* vh, const __nv_bfloat16* vl, int kt, int tid) {
    uint32_t st = sb + AST(stage);
#pragma unroll
    for (int i = 0; i < 4; i++) {
        int g = i * 128 + tid, r = g >> 3, seg = g & 7;
        uint32_t off = SW128(r * 128 + seg * 16);
        size_t so = (base + (size_t)(kt * 64 + r) * 64) * 2 + seg * 16;
        CP_ASYNC16(st + off,         (const char*)kh + so);
        CP_ASYNC16(st + 8192 + off,  (const char*)kl + so);
        CP_ASYNC16(st + 16384 + off, (const char*)vh + so);
        CP_ASYNC16(st + 24576 + off, (const char*)vl + so);
    }
    CP_COMMIT();
}

__global__ __launch_bounds__(128) void attn_mma(
    const __nv_bfloat16* __restrict__ qh, const __nv_bfloat16* __restrict__ ql,
    const __nv_bfloat16* __restrict__ kh, const __nv_bfloat16* __restrict__ kl,
    const __nv_bfloat16* __restrict__ vh, const __nv_bfloat16* __restrict__ vl,
    const float* __restrict__ vsuf, float* __restrict__ out) {
    extern __shared__ char sm[];
    uint32_t sb = (uint32_t)__cvta_generic_to_shared(sm);
    int tid = threadIdx.x, wid = tid >> 5, lane = tid & 31;
    int qt = blockIdx.x, bh = blockIdx.y;
    int b = bh >> 3, h = bh & 7;
    size_t base = (size_t)bh * 1024 * 64;
    int q0 = qt * 64;
    int g = lane >> 2, qd = lane & 3;

    // load Q planes (hi, lo)
#pragma unroll
    for (int i = 0; i < 4; i++) {
        int gg = i * 128 + tid, r = gg >> 3, seg = gg & 7;
        uint32_t off = SW128(r * 128 + seg * 16);
        size_t so = (base + (size_t)(q0 + r) * 64) * 2 + seg * 16;
        CP_ASYNC16(sb + AQH + off, (const char*)qh + so);
        CP_ASYNC16(sb + AQL + off, (const char*)ql + so);
    }
    CP_COMMIT();
    att_load_kv(sb, 0, base, kh, kl, vh, vl, 0, tid);

    float Oa[8][4];
#pragma unroll
    for (int j = 0; j < 8; j++)
#pragma unroll
        for (int e = 0; e < 4; e++) Oa[j][e] = 0.f;
    float mrow0 = 0.f, mrow1 = 0.f, lrow0 = 0.f, lrow1 = 0.f;

    int qA = q0 + wid * 16 + g, qB = qA + 8;
    uint32_t arow = (uint32_t)(wid * 16 + (lane & 15));
    uint32_t acb = (uint32_t)((lane >> 4) << 4);
    int bq = lane >> 3, br = lane & 7;
    uint32_t brbase = (uint32_t)(((bq >> 1) << 3) + br);
    uint32_t bcb = (uint32_t)((bq & 1) << 4);
    uint32_t vrow = (uint32_t)(((lane >> 3) & 1) * 8 + (lane & 7));
    uint32_t vcb = (uint32_t)((lane >> 4) << 4);

    for (int kt = 0; kt <= qt; kt++) {
        if (kt < qt) att_load_kv(sb, (kt + 1) & 1, base, kh, kl, vh, vl, kt + 1, tid);
        if (kt < qt) { CP_WAIT1(); } else { CP_WAIT0(); }
        __syncthreads();
        uint32_t st = sb + AST(kt & 1);

        // ---- S = Q' K'^T (12 k-steps of 16 over [hi|lo|hi]x[hi|hi|lo]) ----
        float Sf[8][4];
#pragma unroll
        for (int j = 0; j < 8; j++)
#pragma unroll
            for (int e = 0; e < 4; e++) Sf[j][e] = 0.f;
#pragma unroll
        for (int ks = 0; ks < 12; ks++) {
            int grp = ks >> 2, kk2 = ks & 3;
            uint32_t qpl = sb + (grp == 1 ? AQL : AQH);
            uint32_t kpl = st + (grp == 2 ? 8192u : 0u);
            uint32_t af[4];
            LDMATRIX_X4(af[0], af[1], af[2], af[3],
                        qpl + SW128(arow * 128 + kk2 * 32 + acb));
#pragma unroll
            for (int np = 0; np < 4; np++) {
                uint32_t bf[4];
                uint32_t boff = SW128((np * 16 + brbase) * 128 + kk2 * 32 + bcb);
                LDMATRIX_X4(bf[0], bf[1], bf[2], bf[3], kpl + boff);
                MMA16816(Sf[2 * np], af, bf[0], bf[1]);
                MMA16816(Sf[2 * np + 1], af, bf[2], bf[3]);
            }
        }

        // ---- mask (exact zeros), scale, online softmax ----
        bool diag = (kt == qt);
        float tm0 = -1e30f, tm1 = -1e30f;
#pragma unroll
        for (int j = 0; j < 8; j++) {
            int k0 = kt * 64 + j * 8 + qd * 2;
            float s0 = Sf[j][0] * 0.125f, s1 = Sf[j][1] * 0.125f;
            float s2 = Sf[j][2] * 0.125f, s3 = Sf[j][3] * 0.125f;
            if (diag) {
                if (k0 > qA) s0 = 0.f;
                if (k0 + 1 > qA) s1 = 0.f;
                if (k0 > qB) s2 = 0.f;
                if (k0 + 1 > qB) s3 = 0.f;
            }
            Sf[j][0] = s0; Sf[j][1] = s1; Sf[j][2] = s2; Sf[j][3] = s3;
            tm0 = fmaxf(tm0, fmaxf(s0, s1));
            tm1 = fmaxf(tm1, fmaxf(s2, s3));
        }
        tm0 = fmaxf(tm0, __shfl_xor_sync(0xffffffffu, tm0, 1));
        tm0 = fmaxf(tm0, __shfl_xor_sync(0xffffffffu, tm0, 2));
        tm1 = fmaxf(tm1, __shfl_xor_sync(0xffffffffu, tm1, 1));
        tm1 = fmaxf(tm1, __shfl_xor_sync(0xffffffffu, tm1, 2));
        float mn0 = fmaxf(mrow0, tm0), mn1 = fmaxf(mrow1, tm1);
        float al0 = __expf(mrow0 - mn0), al1 = __expf(mrow1 - mn1);
        mrow0 = mn0; mrow1 = mn1;
        float ps0 = 0.f, ps1 = 0.f;
#pragma unroll
        for (int j = 0; j < 8; j++) {
            float p0 = __expf(Sf[j][0] - mn0), p1 = __expf(Sf[j][1] - mn0);
            float p2 = __expf(Sf[j][2] - mn1), p3 = __expf(Sf[j][3] - mn1);
            Sf[j][0] = p0; Sf[j][1] = p1; Sf[j][2] = p2; Sf[j][3] = p3;
            ps0 += p0 + p1; ps1 += p2 + p3;
            Oa[j][0] *= al0; Oa[j][1] *= al0; Oa[j][2] *= al1; Oa[j][3] *= al1;
        }
        ps0 += __shfl_xor_sync(0xffffffffu, ps0, 1);
        ps0 += __shfl_xor_sync(0xffffffffu, ps0, 2);
        ps1 += __shfl_xor_sync(0xffffffffu, ps1, 1);
        ps1 += __shfl_xor_sync(0xffffffffu, ps1, 2);
        lrow0 = lrow0 * al0 + ps0;
        lrow1 = lrow1 * al1 + ps1;

        // ---- O += P' V' (register repack, 3-term split) ----
#pragma unroll
        for (int kk = 0; kk < 4; kk++) {
            int j0 = 2 * kk, j1 = 2 * kk + 1;
            float r0, r1;
            uint32_t ah[4], alr[4];
            ah[0] = pack_hi_res(Sf[j0][0], Sf[j0][1], r0, r1); alr[0] = pack2bf(r0, r1);
            ah[1] = pack_hi_res(Sf[j0][2], Sf[j0][3], r0, r1); alr[1] = pack2bf(r0, r1);
            ah[2] = pack_hi_res(Sf[j1][0], Sf[j1][1], r0, r1); alr[2] = pack2bf(r0, r1);
            ah[3] = pack_hi_res(Sf[j1][2], Sf[j1][3], r0, r1); alr[3] = pack2bf(r0, r1);
#pragma unroll
            for (int dg = 0; dg < 4; dg++) {
                uint32_t voff = SW128((kk * 16 + vrow) * 128 + dg * 32 + vcb);
                uint32_t vh0, vh1, vh2, vh3, vl0, vl1, vl2, vl3;
                LDMATRIX_X4T(vh0, vh1, vh2, vh3, st + 16384 + voff);
                LDMATRIX_X4T(vl0, vl1, vl2, vl3, st + 24576 + voff);
                MMA16816(Oa[2 * dg], ah, vh0, vh1);
                MMA16816(Oa[2 * dg], alr, vh0, vh1);
                MMA16816(Oa[2 * dg], ah, vl0, vl1);
                MMA16816(Oa[2 * dg + 1], ah, vh2, vh3);
                MMA16816(Oa[2 * dg + 1], alr, vh2, vh3);
                MMA16816(Oa[2 * dg + 1], ah, vl2, vl3);
            }
        }
        __syncthreads();
    }

    // ---- closed-form future (fully-masked) contribution + write ----
    float wf0 = __expf(-mrow0), wf1 = __expf(-mrow1);
    float nfut = (float)(1024 - (qt + 1) * 64);
    float inv0 = 1.f / (lrow0 + wf0 * nfut);
    float inv1 = 1.f / (lrow1 + wf1 * nfut);
    const float* vs = vsuf + ((size_t)bh * 17 + qt + 1) * 64;
    float* oA = out + ((size_t)(b * 1024) + qA) * 512 + h * 64;
    float* oB = oA + 8 * 512;
#pragma unroll
    for (int j = 0; j < 8; j++) {
        int d = j * 8 + qd * 2;
        float v0 = vs[d], v1 = vs[d + 1];
        *(float2*)&oA[d] = make_float2((Oa[j][0] + wf0 * v0) * inv0,
                                       (Oa[j][1] + wf0 * v1) * inv0);
        *(float2*)&oB[d] = make_float2((Oa[j][2] + wf1 * v0) * inv1,
                                       (Oa[j][3] + wf1 * v1) * inv1);
    }
}

// ---------------- mma.sync GEMM: C[M,N] = A'[M,1536]*B'[N,1536]^T + bias ----
#define STAGE_BYTES 32768
#define SMEM_MMA (3 * STAGE_BYTES)
#define NCHUNK 24

__device__ __forceinline__ void mma_load_chunk(
    uint32_t sbase, int stage,
    const __nv_bfloat16* A, const __nv_bfloat16* Bw,
    int m0, int n0, int c, int tid) {
    uint32_t abase = sbase + stage * STAGE_BYTES;
    uint32_t bbase = abase + 16384;
#pragma unroll
    for (int i = 0; i < 4; i++) {
        int g = i * 256 + tid, row = g >> 3, seg = g & 7;
        uint32_t dst = abase + SW128(row * 128 + seg * 16);
        const char* src = (const char*)A + (size_t)(m0 + row) * 3072 + c * 128 + seg * 16;
        CP_ASYNC16(dst, src);
    }
#pragma unroll
    for (int i = 0; i < 4; i++) {
        int g = i * 256 + tid, row = g >> 3, seg = g & 7;
        uint32_t dst = bbase + SW128(row * 128 + seg * 16);
        const char* src = (const char*)Bw + (size_t)(n0 + row) * 3072 + c * 128 + seg * 16;
        CP_ASYNC16(dst, src);
    }
    CP_COMMIT();
}

template <int RELU>
__global__ __launch_bounds__(256) void gemm_mma(
    const __nv_bfloat16* __restrict__ A, const __nv_bfloat16* __restrict__ Bw,
    const float* __restrict__ bias, float* __restrict__ C, int N) {
    extern __shared__ char smem[];
    uint32_t sbase = (uint32_t)__cvta_generic_to_shared(smem);
    int tid = threadIdx.x, wid = tid >> 5, lane = tid & 31;
    int m0 = blockIdx.y * 128, n0 = blockIdx.x * 128;
    int warp_m = wid & 3, warp_n = wid >> 2;

    float acc[2][8][4];
#pragma unroll
    for (int mt = 0; mt < 2; mt++)
#pragma unroll
        for (int nt = 0; nt < 8; nt++)
#pragma unroll
            for (int e = 0; e < 4; e++) acc[mt][nt][e] = 0.f;

    mma_load_chunk(sbase, 0, A, Bw, m0, n0, 0, tid);
    mma_load_chunk(sbase, 1, A, Bw, m0, n0, 1, tid);

    int a_row = warp_m * 32 + (lane & 15);
    int a_col8 = (lane >> 4) << 3;
    int bq = lane >> 3, br = lane & 7;
    int b_n = warp_n * 64 + ((bq >> 1) << 3) + br;
    int b_col8 = (bq & 1) << 3;

    for (int c = 0; c < NCHUNK; c++) {
        if (c + 1 < NCHUNK) { CP_WAIT1(); } else { CP_WAIT0(); }
        __syncthreads();
        if (c + 2 < NCHUNK)
            mma_load_chunk(sbase, (c + 2) % 3, A, Bw, m0, n0, c + 2, tid);

        uint32_t abase = sbase + (c % 3) * STAGE_BYTES;
        uint32_t bbase = abase + 16384;
#pragma unroll
        for (int ks = 0; ks < 4; ks++) {
            uint32_t af[2][4];
#pragma unroll
            for (int mt = 0; mt < 2; mt++) {
                uint32_t off = (uint32_t)((a_row + mt * 16) * 128 + (ks * 16 + a_col8) * 2);
                LDMATRIX_X4(af[mt][0], af[mt][1], af[mt][2], af[mt][3],
                            abase + SW128(off));
            }
#pragma unroll
            for (int np = 0; np < 4; np++) {
                uint32_t bf[4];
                uint32_t off = (uint32_t)((b_n + np * 16) * 128 + (ks * 16 + b_col8) * 2);
                LDMATRIX_X4(bf[0], bf[1], bf[2], bf[3], bbase + SW128(off));
#pragma unroll
                for (int mt = 0; mt < 2; mt++) {
                    MMA16816(acc[mt][2 * np], af[mt], bf[0], bf[1]);
                    MMA16816(acc[mt][2 * np + 1], af[mt], bf[2], bf[3]);
                }
            }
        }
    }

    int g = lane >> 2, q = lane & 3;
#pragma unroll
    for (int mt = 0; mt < 2; mt++) {
        int row0 = m0 + warp_m * 32 + mt * 16 + g;
#pragma unroll
        for (int nt = 0; nt < 8; nt++) {
            int col = n0 + warp_n * 64 + nt * 8 + q * 2;
            float b0 = bias[col], b1 = bias[col + 1];
            float v0 = acc[mt][nt][0] + b0, v1 = acc[mt][nt][1] + b1;
            float v2 = acc[mt][nt][2] + b0, v3 = acc[mt][nt][3] + b1;
            if (RELU) {
                v0 = fmaxf(v0, 0.f); v1 = fmaxf(v1, 0.f);
                v2 = fmaxf(v2, 0.f); v3 = fmaxf(v3, 0.f);
            }
            *(float2*)&C[(size_t)row0 * N + col] = make_float2(v0, v1);
            *(float2*)&C[(size_t)(row0 + 8) * N + col] = make_float2(v2, v3);
        }
    }
}

// ---------------- int64-vs-int32 detection ----------------------------------
__global__ void detect_kernel(const int* __restrict__ p, int n, int slot) {
    __shared__ int red[256];
    int acc = 0;
    for (int j = 2 * threadIdx.x + 1; j < n; j += 512) acc |= p[j];
    red[threadIdx.x] = acc;
    __syncthreads();
    for (int s = 128; s > 0; s >>= 1) {
        if (threadIdx.x < s) red[threadIdx.x] |= red[threadIdx.x + s];
        __syncthreads();
    }
    if (threadIdx.x == 0) g_is64[slot] = (red[0] == 0) ? 1 : 0;
}

// ---------------- embedding gather ------------------------------------------
__global__ void embed_kernel(const int* __restrict__ inp, const float* __restrict__ emb) {
    int t = blockIdx.x;
    int tok = g_is64[0] ? inp[2 * t] : inp[t];
    const float4* src = (const float4*)(emb + (size_t)tok * E_);
    float4* dst = (float4*)(g_x + (size_t)t * E_);
    for (int i = threadIdx.x; i < E_ / 4; i += blockDim.x) dst[i] = src[i];
}

// ---------------- small SGEMM (head, N=128): 64x64x16 tile ------------------
template <int RELU>
__global__ __launch_bounds__(256) void sgemm_nt(
    const float* __restrict__ A, const float* __restrict__ B,
    const float* __restrict__ bias, float* __restrict__ C, int N, int K) {
    __shared__ float As[16][64];
    __shared__ float Bs[16][64];
    int tid = threadIdx.x;
    int tx = tid & 15, ty = tid >> 4;
    int m0 = blockIdx.y * 64, n0 = blockIdx.x * 64;
    int lr = tid >> 2;
    int lc = (tid & 3) * 4;
    const float* Ap = A + (size_t)(m0 + lr) * K + lc;
    const float* Bp = B + (size_t)(n0 + lr) * K + lc;
    float acc[4][4] = {};
    for (int k0 = 0; k0 < K; k0 += 16) {
        float4 a = *(const float4*)(Ap + k0);
        float4 b = *(const float4*)(Bp + k0);
        As[lc + 0][lr] = a.x; As[lc + 1][lr] = a.y; As[lc + 2][lr] = a.z; As[lc + 3][lr] = a.w;
        Bs[lc + 0][lr] = b.x; Bs[lc + 1][lr] = b.y; Bs[lc + 2][lr] = b.z; Bs[lc + 3][lr] = b.w;
        __syncthreads();
#pragma unroll
        for (int kk = 0; kk < 16; kk++) {
            float4 av = *(const float4*)&As[kk][ty * 4];
            float4 bv = *(const float4*)&Bs[kk][tx * 4];
            float ar[4] = {av.x, av.y, av.z, av.w};
            float br[4] = {bv.x, bv.y, bv.z, bv.w};
#pragma unroll
            for (int i = 0; i < 4; i++)
#pragma unroll
                for (int j = 0; j < 4; j++) acc[i][j] += ar[i] * br[j];
        }
        __syncthreads();
    }
    float b0 = bias[n0 + tx * 4 + 0];
    float b1 = bias[n0 + tx * 4 + 1];
    float b2 = bias[n0 + tx * 4 + 2];
    float b3 = bias[n0 + tx * 4 + 3];
#pragma unroll
    for (int i = 0; i < 4; i++) {
        float4 v;
        v.x = acc[i][0] + b0; v.y = acc[i][1] + b1;
        v.z = acc[i][2] + b2; v.w = acc[i][3] + b3;
        if (RELU) {
            v.x = fmaxf(v.x, 0.f); v.y = fmaxf(v.y, 0.f);
            v.z = fmaxf(v.z, 0.f); v.w = fmaxf(v.w, 0.f);
        }
        *(float4*)&C[(size_t)(m0 + ty * 4 + i) * N + n0 + tx * 4] = v;
    }
}

// ---------------- fused residual-add + layernorm ----------------------------
__global__ __launch_bounds__(128) void add_ln_kernel(
    const float* __restrict__ A, const float* __restrict__ R,
    const float* __restrict__ sc, const float* __restrict__ bi,
    float* __restrict__ out) {
    __shared__ float red[4], red2[4];
    int t = blockIdx.x, tid = threadIdx.x;
    int e0 = tid * 4;
    float4 a = *(const float4*)&A[(size_t)t * E_ + e0];
    float4 r = *(const float4*)&R[(size_t)t * E_ + e0];
    float v0 = a.x + r.x, v1 = a.y + r.y, v2 = a.z + r.z, v3 = a.w + r.w;
    float sum = v0 + v1 + v2 + v3;
#pragma unroll
    for (int o = 16; o; o >>= 1) sum += __shfl_xor_sync(0xffffffffu, sum, o);
    int w = tid >> 5, lane = tid & 31;
    if (lane == 0) red[w] = sum;
    __syncthreads();
    sum = red[0] + red[1] + red[2] + red[3];
    float mu = sum * (1.f / E_);
    float d0 = v0 - mu, d1 = v1 - mu, d2 = v2 - mu, d3 = v3 - mu;
    float sq = d0 * d0 + d1 * d1 + d2 * d2 + d3 * d3;
#pragma unroll
    for (int o = 16; o; o >>= 1) sq += __shfl_xor_sync(0xffffffffu, sq, o);
    if (lane == 0) red2[w] = sq;
    __syncthreads();
    sq = red2[0] + red2[1] + red2[2] + red2[3];
    float rstd = rsqrtf(sq * (1.f / E_) + 1e-5f);
    float4 s4 = *(const float4*)&sc[e0];
    float4 b4 = *(const float4*)&bi[e0];
    float4 o4;
    o4.x = d0 * rstd * s4.x + b4.x;
    o4.y = d1 * rstd * s4.y + b4.y;
    o4.z = d2 * rstd * s4.z + b4.z;
    o4.w = d3 * rstd * s4.w + b4.w;
    *(float4*)&out[(size_t)t * E_ + e0] = o4;
}

// ---------------- loss ------------------------------------------------------
__global__ void zero_loss(float* p) { *p = 0.f; }

__global__ __launch_bounds__(256) void loss_kernel(
    const float* __restrict__ logits, const int* __restrict__ tgt,
    float* __restrict__ loss_out) {
    int warp = threadIdx.x >> 5, lane = threadIdx.x & 31;
    int t = blockIdx.x * 8 + warp;
    const float* lp = logits + (size_t)t * V_;
    float x[4];
    float mx = -1e30f, tot = 0.f;
#pragma unroll
    for (int i = 0; i < 4; i++) {
        x[i] = lp[lane + 32 * i];
        mx = fmaxf(mx, x[i]);
        tot += x[i];
    }
#pragma unroll
    for (int o = 16; o; o >>= 1) mx = fmaxf(mx, __shfl_xor_sync(0xffffffffu, mx, o));
    float s = 0.f;
#pragma unroll
    for (int i = 0; i < 4; i++) s += expf(x[i] - mx);
#pragma unroll
    for (int o = 16; o; o >>= 1) {
        s += __shfl_xor_sync(0xffffffffu, s, o);
        tot += __shfl_xor_sync(0xffffffffu, tot, o);
    }
    if (lane == 0) {
        float logZ = mx + logf(s);
        int tv = g_is64[1] ? tgt[2 * t] : tgt[t];
        float nll = logZ - lp[tv];
        float smooth = logZ - tot * (1.f / V_);
        atomicAdd(loss_out, ((1.f - EPS_) * nll + EPS_ * smooth) * (1.f / BT));
    }
}

// ---------------- driver -----------------------------------------------------
extern "C" void kernel_launch(void* const* d_in, const int* in_sizes, int n_in,
                              void* d_out, int out_size) {
    const int*   inputs  = (const int*)d_in[0];
    const int*   targets = (const int*)d_in[1];
    const float* emb     = (const float*)d_in[2];
    const float* qkv_w   = (const float*)d_in[3];
    const float* qkv_b   = (const float*)d_in[4];
    const float* aff1_w  = (const float*)d_in[5];
    const float* aff1_b  = (const float*)d_in[6];
    const float* aff2_w  = (const float*)d_in[7];
    const float* aff2_b  = (const float*)d_in[8];
    const float* ffn1_w  = (const float*)d_in[9];
    const float* ffn1_b  = (const float*)d_in[10];
    const float* ffn2_w  = (const float*)d_in[11];
    const float* ffn2_b  = (const float*)d_in[12];
    const float* ln1_s   = (const float*)d_in[13];
    const float* ln1_b   = (const float*)d_in[14];
    const float* ln2_s   = (const float*)d_in[15];
    const float* ln2_b   = (const float*)d_in[16];
    const float* head_w  = (const float*)d_in[17];
    const float* head_b  = (const float*)d_in[18];
    float* out = (float*)d_out;

    cudaFuncSetAttribute(gemm_mma<0>, cudaFuncAttributeMaxDynamicSharedMemorySize, SMEM_MMA);
    cudaFuncSetAttribute(gemm_mma<1>, cudaFuncAttributeMaxDynamicSharedMemorySize, SMEM_MMA);
    cudaFuncSetAttribute(attn_mma, cudaFuncAttributeMaxDynamicSharedMemorySize, ATT_SMEM);

    float *px, *pqkv, *pa, *ph, *pb, *po1, *pvsuf;
    __nv_bfloat16 *pab, *pwqkv, *pw1, *pw2, *pw3, *pw4;
    __nv_bfloat16 *pqh, *pql, *pkh, *pkl, *pvh, *pvl;
    cudaGetSymbolAddress((void**)&px,   g_x);
    cudaGetSymbolAddress((void**)&pqkv, g_qkv);
    cudaGetSymbolAddress((void**)&pa,   g_a);
    cudaGetSymbolAddress((void**)&ph,   g_h);
    cudaGetSymbolAddress((void**)&pb,   g_b2);
    cudaGetSymbolAddress((void**)&po1,  g_o1);
    cudaGetSymbolAddress((void**)&pab,  g_abig);
    cudaGetSymbolAddress((void**)&pwqkv, g_wqkv);
    cudaGetSymbolAddress((void**)&pw1,  g_w1);
    cudaGetSymbolAddress((void**)&pw2,  g_w2);
    cudaGetSymbolAddress((void**)&pw3,  g_w3);
    cudaGetSymbolAddress((void**)&pw4,  g_w4);
    cudaGetSymbolAddress((void**)&pqh,  g_qh);
    cudaGetSymbolAddress((void**)&pql,  g_ql);
    cudaGetSymbolAddress((void**)&pkh,  g_kh);
    cudaGetSymbolAddress((void**)&pkl,  g_kl);
    cudaGetSymbolAddress((void**)&pvh,  g_vh);
    cudaGetSymbolAddress((void**)&pvl,  g_vl);
    cudaGetSymbolAddress((void**)&pvsuf, g_vsuf);

    detect_kernel<<<1, 256>>>(inputs, BT, 0);
    detect_kernel<<<1, 256>>>(targets, BT, 1);
    embed_kernel<<<BT, 128>>>(inputs, emb);

    conv_split<0><<<L_ * 1536, 128>>>(qkv_w,  pwqkv);
    conv_split<0><<<L_ * 512, 128>>>(aff1_w, pw1);
    conv_split<0><<<L_ * 512, 128>>>(aff2_w, pw2);
    conv_split<0><<<L_ * 512, 128>>>(ffn1_w, pw3);
    conv_split<0><<<L_ * 512, 128>>>(ffn2_w, pw4);

    for (int l = 0; l < L_; l++) {
        conv_split<1><<<BT, 128>>>(px, pab);
        gemm_mma<0><<<dim3(12, 32), 256, SMEM_MMA>>>(
            pab, pwqkv + (size_t)l * 1536 * KB3, qkv_b + (size_t)l * 1536, pqkv, 1536);
        conv_qkv<<<dim3(BT, H_), 64>>>(pqkv, pqh, pql, pkh, pkl, pvh, pvl);
        vsuf_kernel<<<32, 64>>>(pqkv, pvsuf);
        attn_mma<<<dim3(16, 32), 128, ATT_SMEM>>>(pqh, pql, pkh, pkl, pvh, pvl,
                                                  pvsuf, pa);
        conv_split<1><<<BT, 128>>>(pa, pab);
        gemm_mma<1><<<dim3(4, 32), 256, SMEM_MMA>>>(
            pab, pw1 + (size_t)l * 512 * KB3, aff1_b + (size_t)l * 512, ph, 512);
        conv_split<1><<<BT, 128>>>(ph, pab);
        gemm_mma<0><<<dim3(4, 32), 256, SMEM_MMA>>>(
            pab, pw2 + (size_t)l * 512 * KB3, aff2_b + (size_t)l * 512, pb, 512);
        add_ln_kernel<<<BT, 128>>>(pb, px, ln1_s + (size_t)l * 512,
                                   ln1_b + (size_t)l * 512, po1);
        conv_split<1><<<BT, 128>>>(po1, pab);
        gemm_mma<1><<<dim3(4, 32), 256, SMEM_MMA>>>(
            pab, pw3 + (size_t)l * 512 * KB3, ffn1_b + (size_t)l * 512, ph, 512);
        conv_split<1><<<BT, 128>>>(ph, pab);
        gemm_mma<0><<<dim3(4, 32), 256, SMEM_MMA>>>(
            pab, pw4 + (size_t)l * 512 * KB3, ffn2_b + (size_t)l * 512, pb, 512);
        add_ln_kernel<<<BT, 128>>>(po1, pb, ln2_s + (size_t)l * 512,
                                   ln2_b + (size_t)l * 512, px);
    }

    float* logits_dst = (out_size >= BT * V_) ? out : pqkv;
    sgemm_nt<0><<<dim3(2, 64), 256>>>(px, head_w, head_b, logits_dst, V_, 512);

    float* loss_dst = nullptr;
    if (out_size > BT * V_) loss_dst = out + BT * V_;
    else if (out_size < BT * V_ && out_size >= 1) loss_dst = out;
    if (loss_dst) {
        zero_loss<<<1, 1>>>(loss_dst);
        loss_kernel<<<BT / 8, 256>>>(logits_dst, targets, loss_dst);
    }
}